// round 5
// baseline (speedup 1.0000x reference)
#include <cuda_runtime.h>
#include <cstdint>

#define BATCH 512
#define NV 6890
#define N3 20670      // NV*3
#define NP 20736      // padded N: 162*128 = 6912*3
#define KDIM 224      // 207 + 10 + 7 pad
#define NJ 24
#define J54 54
#define NSEG 8
#define SEGLEN 864
#define KC 16

__constant__ int c_parent[23] = {0, 0, 0, 1, 2, 3, 4, 5, 6, 7, 8, 9,
                                 9, 9, 12, 13, 14, 16, 17, 18, 19, 20, 21};

// ---- scratch ----
__device__ float g_JM[NJ * 3 * 11];
__device__ float g_Acat[BATCH * KDIM];        // fp32 [lrotmin|beta|0]
__device__ float g_At[KDIM * BATCH];          // transposed, tf32-rounded
__device__ float g_Gc[BATCH * NJ * 12];
__device__ float g_Wt[KDIM * NP];             // k-major packed, tf32-rounded
__device__ float g_vposed[BATCH * N3];
__device__ float g_part[NSEG * BATCH * J54 * 3];
__device__ float g_pel[BATCH * 3];
__device__ int g_jmap64;
__device__ int g_prow[2];                     // jmap[27], jmap[28]
__device__ float g_u[6912];                   // 0.5*(row_a + row_c), padded
__device__ float g_rowsum[J54];
__device__ float g_s0[NJ * 4];                // sum_v u*w*[vt;1]
__device__ float g_Ppart[NSEG * 14 * 384 * 3];
__device__ float g_P[NJ * 3 * KDIM];          // [j][d][k]

__device__ __forceinline__ float to_tf32(float v) {
    uint32_t o;
    asm("cvt.rna.tf32.f32 %0, %1;" : "=r"(o) : "f"(v));
    return __uint_as_float(o);
}

__device__ __forceinline__ void mma_tf32(float* c, const uint32_t* a, const uint32_t* b) {
    asm volatile(
        "mma.sync.aligned.m16n8k8.row.col.f32.tf32.tf32.f32 "
        "{%0,%1,%2,%3}, {%4,%5,%6,%7}, {%8,%9}, {%0,%1,%2,%3};\n"
        : "+f"(c[0]), "+f"(c[1]), "+f"(c[2]), "+f"(c[3])
        : "r"(a[0]), "r"(a[1]), "r"(a[2]), "r"(a[3]), "r"(b[0]), "r"(b[1]));
}

__device__ __forceinline__ const float* reg_row(int r, const float* Jreg,
                                                const float* Jspin, const float* Jextra) {
    return (r < 24) ? (Jreg + r * NV)
         : (r < 45) ? (Jspin + (r - 24) * NV)
                    : (Jextra + (r - 45) * NV);
}

// ============================================================================
__global__ void sniff_kernel(const int* __restrict__ jmap) {
    if (threadIdx.x == 0) {
        int is64 = 1;
        for (int i = 0; i < 24; i++)
            if (jmap[2 * i + 1] != 0) is64 = 0;
        g_jmap64 = is64;
        g_prow[0] = is64 ? jmap[54] : jmap[27];
        g_prow[1] = is64 ? jmap[56] : jmap[28];
    }
}

// ============================================================================
__global__ void urow_kernel(const float* __restrict__ Jreg,
                            const float* __restrict__ Jspin,
                            const float* __restrict__ Jextra) {
    int v = blockIdx.x * 256 + threadIdx.x;   // grid covers 6912
    if (v >= 6912) return;
    float val = 0.f;
    if (v < NV) {
        const float* ra = reg_row(g_prow[0], Jreg, Jspin, Jextra);
        const float* rc = reg_row(g_prow[1], Jreg, Jspin, Jextra);
        val = 0.5f * (ra[v] + rc[v]);
    }
    g_u[v] = val;
}

// ============================================================================
__global__ void jm_kernel(const float* __restrict__ Jreg,
                          const float* __restrict__ shapedirs,
                          const float* __restrict__ vtemp) {
    int j = blockIdx.x / 3, d = blockIdx.x % 3;
    int t = threadIdx.x;
    float acc[11];
#pragma unroll
    for (int k = 0; k < 11; k++) acc[k] = 0.f;
    const float* reg = Jreg + j * NV;
    for (int v = t; v < NV; v += 256) {
        float r = reg[v];
        const float* sd = shapedirs + (v * 3 + d) * 10;
#pragma unroll
        for (int k = 0; k < 10; k++) acc[k] += r * sd[k];
        acc[10] += r * vtemp[v * 3 + d];
    }
    __shared__ float red[256];
    for (int k = 0; k < 11; k++) {
        red[t] = acc[k];
        __syncthreads();
        for (int s = 128; s > 0; s >>= 1) {
            if (t < s) red[t] += red[t + s];
            __syncthreads();
        }
        if (t == 0) g_JM[(j * 3 + d) * 11 + k] = red[0];
        __syncthreads();
    }
}

// ============================================================================
// smalls: blocks 0..53 -> rowsum[r]; blocks 54..77 -> s0[j][4]
// ============================================================================
__global__ void smalls_kernel(const float* __restrict__ Jreg,
                              const float* __restrict__ Jspin,
                              const float* __restrict__ Jextra,
                              const float* __restrict__ weights,
                              const float* __restrict__ vtemp) {
    int blk = blockIdx.x, t = threadIdx.x;
    __shared__ float red[4][256];
    if (blk < J54) {
        const float* row = reg_row(blk, Jreg, Jspin, Jextra);
        float s = 0.f;
        for (int v = t; v < NV; v += 256) s += row[v];
        red[0][t] = s;
        __syncthreads();
        for (int st = 128; st > 0; st >>= 1) {
            if (t < st) red[0][t] += red[0][t + st];
            __syncthreads();
        }
        if (t == 0) g_rowsum[blk] = red[0][0];
    } else {
        int j = blk - J54;
        float s0 = 0.f, s1 = 0.f, s2 = 0.f, s3 = 0.f;
        for (int v = t; v < NV; v += 256) {
            float uw = g_u[v] * weights[v * NJ + j];
            s0 += uw * vtemp[v * 3 + 0];
            s1 += uw * vtemp[v * 3 + 1];
            s2 += uw * vtemp[v * 3 + 2];
            s3 += uw;
        }
        red[0][t] = s0; red[1][t] = s1; red[2][t] = s2; red[3][t] = s3;
        __syncthreads();
        for (int st = 128; st > 0; st >>= 1) {
            if (t < st) {
                red[0][t] += red[0][t + st];
                red[1][t] += red[1][t + st];
                red[2][t] += red[2][t + st];
                red[3][t] += red[3][t + st];
            }
            __syncthreads();
        }
        if (t == 0) {
            g_s0[j * 4 + 0] = red[0][0];
            g_s0[j * 4 + 1] = red[1][0];
            g_s0[j * 4 + 2] = red[2][0];
            g_s0[j * 4 + 3] = red[3][0];
        }
    }
}

// ============================================================================
// pose: rodrigues, chain, Gc; also writes tf32-transposed At
// ============================================================================
__global__ void pose_kernel(const float* __restrict__ pose,
                            const float* __restrict__ beta) {
    int b = blockIdx.x, t = threadIdx.x;
    __shared__ float sR[NJ][9];
    __shared__ float sJ[NJ][3];
    __shared__ float sA[NJ][12];

    if (t < NJ) {
        float rx = pose[b * 72 + 3 * t + 0];
        float ry = pose[b * 72 + 3 * t + 1];
        float rz = pose[b * 72 + 3 * t + 2];
        float th = sqrtf(rx * rx + ry * ry + rz * rz);
        float inv = 1.f / fmaxf(th, 1e-8f);
        float kx = rx * inv, ky = ry * inv, kz = rz * inv;
        float s = sinf(th), c = cosf(th), C = 1.f - c;
        float kn2 = kx * kx + ky * ky + kz * kz;
        float R[9];
        R[0] = 1.f + C * (kx * kx - kn2);
        R[1] = -s * kz + C * kx * ky;
        R[2] = s * ky + C * kx * kz;
        R[3] = s * kz + C * ky * kx;
        R[4] = 1.f + C * (ky * ky - kn2);
        R[5] = -s * kx + C * ky * kz;
        R[6] = -s * ky + C * kz * kx;
        R[7] = s * kx + C * kz * ky;
        R[8] = 1.f + C * (kz * kz - kn2);
#pragma unroll
        for (int e = 0; e < 9; e++) sR[t][e] = R[e];
        if (t >= 1) {
            float* dst = g_Acat + b * KDIM + (t - 1) * 9;
#pragma unroll
            for (int e = 0; e < 9; e++) {
                float val = R[e] - ((e == 0 || e == 4 || e == 8) ? 1.f : 0.f);
                dst[e] = val;
                g_At[((t - 1) * 9 + e) * BATCH + b] = to_tf32(val);
            }
        }
#pragma unroll
        for (int d = 0; d < 3; d++) {
            const float* m = g_JM + (t * 3 + d) * 11;
            float val = m[10];
#pragma unroll
            for (int k = 0; k < 10; k++) val += m[k] * beta[b * 10 + k];
            sJ[t][d] = val;
        }
    }
    if (t == 0) {
#pragma unroll
        for (int k = 0; k < 10; k++) {
            float bv = beta[b * 10 + k];
            g_Acat[b * KDIM + 207 + k] = bv;
            g_At[(207 + k) * BATCH + b] = to_tf32(bv);
        }
#pragma unroll
        for (int k = 217; k < KDIM; k++) {
            g_Acat[b * KDIM + k] = 0.f;
            g_At[k * BATCH + b] = 0.f;
        }
    }
    __syncwarp();
    if (t == 0) {
#pragma unroll
        for (int e = 0; e < 9; e++) sA[0][(e / 3) * 4 + (e % 3)] = sR[0][e];
        sA[0][3] = sJ[0][0]; sA[0][7] = sJ[0][1]; sA[0][11] = sJ[0][2];
        for (int i = 1; i < NJ; i++) {
            int p = c_parent[i - 1];
            float lt0 = sJ[i][0] - sJ[p][0];
            float lt1 = sJ[i][1] - sJ[p][1];
            float lt2 = sJ[i][2] - sJ[p][2];
            for (int r = 0; r < 3; r++) {
                float p0 = sA[p][r * 4 + 0], p1 = sA[p][r * 4 + 1];
                float p2 = sA[p][r * 4 + 2], p3 = sA[p][r * 4 + 3];
                for (int cc = 0; cc < 3; cc++)
                    sA[i][r * 4 + cc] = p0 * sR[i][0 * 3 + cc] + p1 * sR[i][1 * 3 + cc] + p2 * sR[i][2 * 3 + cc];
                sA[i][r * 4 + 3] = p0 * lt0 + p1 * lt1 + p2 * lt2 + p3;
            }
        }
    }
    __syncwarp();
    if (t < NJ) {
        float j0 = sJ[t][0], j1 = sJ[t][1], j2 = sJ[t][2];
        float* dst = g_Gc + (b * NJ + t) * 12;
#pragma unroll
        for (int r = 0; r < 3; r++) {
            float a0 = sA[t][r * 4 + 0], a1 = sA[t][r * 4 + 1];
            float a2 = sA[t][r * 4 + 2], a3 = sA[t][r * 4 + 3];
            dst[r * 4 + 0] = a0; dst[r * 4 + 1] = a1; dst[r * 4 + 2] = a2;
            dst[r * 4 + 3] = a3 - (a0 * j0 + a1 * j1 + a2 * j2);
        }
    }
}

// ============================================================================
__global__ void pack_kernel(const float* __restrict__ posedirs,
                            const float* __restrict__ shapedirs) {
    __shared__ float s[32 * 225];
    int n0 = blockIdx.x * 32;
    int t = threadIdx.x;
    for (int idx = t; idx < 32 * 207; idx += 256) {
        int n = idx / 207, k = idx % 207;
        int gn = n0 + n;
        s[n * 225 + k] = (gn < N3) ? posedirs[gn * 207 + k] : 0.f;
    }
    for (int idx = t; idx < 32 * 10; idx += 256) {
        int n = idx / 10, k = idx % 10;
        int gn = n0 + n;
        s[n * 225 + 207 + k] = (gn < N3) ? shapedirs[gn * 10 + k] : 0.f;
    }
    for (int idx = t; idx < 32 * 7; idx += 256) {
        int n = idx / 7, k = idx % 7;
        s[n * 225 + 217 + k] = 0.f;
    }
    __syncthreads();
    for (int idx = t; idx < KDIM * 32; idx += 256) {
        int k = idx / 32, n = idx % 32;
        g_Wt[k * NP + n0 + n] = to_tf32(s[n * 225 + k]);
    }
}

// ============================================================================
// pelpre: P partials. grid(14 kblocks, 8 vsegs), 384 threads.
// ============================================================================
__global__ void __launch_bounds__(384) pelpre_kernel(const float* __restrict__ weights) {
    int kb = blockIdx.x, seg = blockIdx.y;
    int tid = threadIdx.x;
    int j = tid >> 4, kk = tid & 15;
    __shared__ float su[32];
    __shared__ float sw[32][25];
    __shared__ float sWt[16][97];
    float a0 = 0.f, a1 = 0.f, a2 = 0.f;
    for (int c = 0; c < 27; c++) {
        int v0 = seg * SEGLEN + c * 32;
        __syncthreads();
        if (tid < 32) su[tid] = g_u[v0 + tid];
        for (int i = tid; i < 32 * NJ; i += 384) {
            int vv = i / NJ, jj = i % NJ;
            int v = v0 + vv;
            sw[vv][jj] = (v < NV) ? weights[v * NJ + jj] : 0.f;
        }
        for (int i = tid; i < 16 * 96; i += 384) {
            int r = i / 96, x = i % 96;
            sWt[r][x] = g_Wt[(size_t)(kb * 16 + r) * NP + v0 * 3 + x];
        }
        __syncthreads();
#pragma unroll 8
        for (int vv = 0; vv < 32; vv++) {
            float rw = su[vv] * sw[vv][j];
            a0 += rw * sWt[kk][vv * 3 + 0];
            a1 += rw * sWt[kk][vv * 3 + 1];
            a2 += rw * sWt[kk][vv * 3 + 2];
        }
    }
    float* dst = g_Ppart + ((size_t)(seg * 14 + kb) * 384 + tid) * 3;
    dst[0] = a0; dst[1] = a1; dst[2] = a2;
}

// ============================================================================
__global__ void pelred_kernel() {
    int i = blockIdx.x * 256 + threadIdx.x;   // < 16128
    if (i >= 14 * 384 * 3) return;
    int d = i % 3, s = i / 3;
    int kb = s / 384, slot = s % 384;
    int j = slot >> 4, kk = slot & 15;
    float sum = 0.f;
#pragma unroll
    for (int seg = 0; seg < NSEG; seg++)
        sum += g_Ppart[((size_t)(seg * 14 + kb) * 384 + slot) * 3 + d];
    g_P[j * (3 * KDIM) + d * KDIM + kb * 16 + kk] = sum;
}

// ============================================================================
// pelvis: per batch, q_j = s0_j + P_j @ a_b; pel = sum_j Gc[b,j] @ [q;qw]
// ============================================================================
__global__ void __launch_bounds__(256) pelvis_kernel() {
    __shared__ float sA[32][KDIM];
    int b0 = blockIdx.x * 32;
    int tid = threadIdx.x;
    for (int i = tid; i < 32 * (KDIM / 4); i += 256) {
        int bb = i / (KDIM / 4), q4 = i % (KDIM / 4);
        ((float4*)&sA[bb][0])[q4] = ((const float4*)(g_Acat + (size_t)(b0 + bb) * KDIM))[q4];
    }
    __syncthreads();
    int bb = tid >> 3, g = tid & 7;
    int b = b0 + bb;
    float px = 0.f, py = 0.f, pz = 0.f;
#pragma unroll
    for (int jj = 0; jj < 3; jj++) {
        int j = g * 3 + jj;
        float q[3];
#pragma unroll
        for (int d = 0; d < 3; d++) {
            const float4* pr = (const float4*)(g_P + j * (3 * KDIM) + d * KDIM);
            const float4* ar = (const float4*)&sA[bb][0];
            float s = 0.f;
#pragma unroll 8
            for (int k4 = 0; k4 < KDIM / 4; k4++) {
                float4 p = pr[k4], a = ar[k4];
                s += p.x * a.x + p.y * a.y + p.z * a.z + p.w * a.w;
            }
            q[d] = g_s0[j * 4 + d] + s;
        }
        float qw = g_s0[j * 4 + 3];
        const float* gc = g_Gc + (size_t)(b * NJ + j) * 12;
        px += gc[0] * q[0] + gc[1] * q[1] + gc[2] * q[2] + gc[3] * qw;
        py += gc[4] * q[0] + gc[5] * q[1] + gc[6] * q[2] + gc[7] * qw;
        pz += gc[8] * q[0] + gc[9] * q[1] + gc[10] * q[2] + gc[11] * qw;
    }
#pragma unroll
    for (int off = 4; off > 0; off >>= 1) {
        px += __shfl_down_sync(0xffffffff, px, off, 8);
        py += __shfl_down_sync(0xffffffff, py, off, 8);
        pz += __shfl_down_sync(0xffffffff, pz, off, 8);
    }
    if (g == 0) {
        g_pel[b * 3 + 0] = px;
        g_pel[b * 3 + 1] = py;
        g_pel[b * 3 + 2] = pz;
    }
}

// ============================================================================
// GEMM TF32: v_posed = At^T @ Wt + vtemp. grid(m-tiles fastest, n-tiles)
// ============================================================================
__global__ void __launch_bounds__(256, 2) gemm_tf32_kernel(const float* __restrict__ vtemp) {
    __shared__ __align__(16) float As[2][KC][132];
    __shared__ __align__(16) float Bs[2][KC][132];
    int tid = threadIdx.x;
    int lane = tid & 31, wid = tid >> 5;
    int warp_m = wid & 1, warp_n = wid >> 1;
    int gq = lane >> 2, tq = lane & 3;
    int m0 = blockIdx.x * 128;
    int n0 = blockIdx.y * 128;

    float acc[4][4][4];
#pragma unroll
    for (int mt = 0; mt < 4; mt++)
#pragma unroll
        for (int nt = 0; nt < 4; nt++)
#pragma unroll
            for (int i = 0; i < 4; i++) acc[mt][nt][i] = 0.f;

    const int NSTAGE = KDIM / KC;

#define LOAD_STAGE(s, buf)                                                          \
    {                                                                               \
        int k0 = (s) * KC;                                                          \
        _Pragma("unroll")                                                           \
        for (int i = 0; i < 2; i++) {                                               \
            int idx = tid + i * 256;                                                \
            int k = idx >> 5, mg = (idx & 31) << 2;                                 \
            unsigned da = (unsigned)__cvta_generic_to_shared(&As[buf][k][mg]);      \
            const float* sa = g_At + (k0 + k) * BATCH + m0 + mg;                    \
            asm volatile("cp.async.cg.shared.global [%0], [%1], 16;" ::"r"(da), "l"(sa)); \
            unsigned db = (unsigned)__cvta_generic_to_shared(&Bs[buf][k][mg]);      \
            const float* sb = g_Wt + (size_t)(k0 + k) * NP + n0 + mg;               \
            asm volatile("cp.async.cg.shared.global [%0], [%1], 16;" ::"r"(db), "l"(sb)); \
        }                                                                           \
        asm volatile("cp.async.commit_group;");                                     \
    }

    LOAD_STAGE(0, 0);
    for (int s = 0; s < NSTAGE; s++) {
        int buf = s & 1;
        if (s + 1 < NSTAGE) {
            LOAD_STAGE(s + 1, buf ^ 1);
            asm volatile("cp.async.wait_group 1;");
        } else {
            asm volatile("cp.async.wait_group 0;");
        }
        __syncthreads();
#pragma unroll
        for (int kk = 0; kk < KC / 8; kk++) {
            int kb = kk * 8;
            uint32_t af[4][4], bf[4][2];
#pragma unroll
            for (int mt = 0; mt < 4; mt++) {
                int r = warp_m * 64 + mt * 16 + gq;
                af[mt][0] = __float_as_uint(As[buf][kb + tq][r]);
                af[mt][1] = __float_as_uint(As[buf][kb + tq][r + 8]);
                af[mt][2] = __float_as_uint(As[buf][kb + tq + 4][r]);
                af[mt][3] = __float_as_uint(As[buf][kb + tq + 4][r + 8]);
            }
#pragma unroll
            for (int nt = 0; nt < 4; nt++) {
                int cn = warp_n * 32 + nt * 8 + gq;
                bf[nt][0] = __float_as_uint(Bs[buf][kb + tq][cn]);
                bf[nt][1] = __float_as_uint(Bs[buf][kb + tq + 4][cn]);
            }
#pragma unroll
            for (int mt = 0; mt < 4; mt++)
#pragma unroll
                for (int nt = 0; nt < 4; nt++)
                    mma_tf32(acc[mt][nt], af[mt], bf[nt]);
        }
        __syncthreads();
    }

#pragma unroll
    for (int mt = 0; mt < 4; mt++) {
        int row = m0 + warp_m * 64 + mt * 16 + gq;
#pragma unroll
        for (int nt = 0; nt < 4; nt++) {
            int cn = n0 + warp_n * 32 + nt * 8 + 2 * tq;
            if (cn < N3) {
                float2 vt = *(const float2*)(vtemp + cn);
                float2 o0 = {acc[mt][nt][0] + vt.x, acc[mt][nt][1] + vt.y};
                float2 o1 = {acc[mt][nt][2] + vt.x, acc[mt][nt][3] + vt.y};
                *(float2*)(g_vposed + (size_t)row * N3 + cn) = o0;
                *(float2*)(g_vposed + (size_t)(row + 8) * N3 + cn) = o1;
            }
        }
    }
#undef LOAD_STAGE
}

// ============================================================================
// skin: 128 verts x 16 batches per block; writes v - pelvis to out
// ============================================================================
__global__ void __launch_bounds__(128) skin_kernel(const float* __restrict__ weights,
                                                   float* __restrict__ out) {
    __shared__ __align__(16) float sGc[16 * NJ * 12];
    __shared__ float spel[16 * 3];
    int b0 = blockIdx.y * 16;
    int v = blockIdx.x * 128 + threadIdx.x;
    for (int idx = threadIdx.x; idx < 16 * NJ * 12; idx += 128)
        sGc[idx] = g_Gc[(size_t)b0 * NJ * 12 + idx];
    if (threadIdx.x < 48) spel[threadIdx.x] = g_pel[b0 * 3 + threadIdx.x];
    __syncthreads();
    if (v >= NV) return;
    float w[NJ];
#pragma unroll
    for (int j = 0; j < NJ; j++) w[j] = weights[v * NJ + j];
#pragma unroll 1
    for (int bb = 0; bb < 16; bb++) {
        const float* vp = g_vposed + (size_t)(b0 + bb) * N3 + v * 3;
        float p0 = vp[0], p1 = vp[1], p2 = vp[2];
        float T[12];
#pragma unroll
        for (int c = 0; c < 12; c++) T[c] = 0.f;
        const float4* gc = (const float4*)(sGc + bb * NJ * 12);
#pragma unroll
        for (int j = 0; j < NJ; j++) {
            float wj = w[j];
            float4 r0 = gc[j * 3 + 0];
            float4 r1 = gc[j * 3 + 1];
            float4 r2 = gc[j * 3 + 2];
            T[0] += wj * r0.x; T[1] += wj * r0.y; T[2] += wj * r0.z; T[3] += wj * r0.w;
            T[4] += wj * r1.x; T[5] += wj * r1.y; T[6] += wj * r1.z; T[7] += wj * r1.w;
            T[8] += wj * r2.x; T[9] += wj * r2.y; T[10] += wj * r2.z; T[11] += wj * r2.w;
        }
        float* o = out + (size_t)(b0 + bb) * N3 + v * 3;
        o[0] = T[0] * p0 + T[1] * p1 + T[2] * p2 + T[3] - spel[bb * 3 + 0];
        o[1] = T[4] * p0 + T[5] * p1 + T[6] * p2 + T[7] - spel[bb * 3 + 1];
        o[2] = T[8] * p0 + T[9] * p1 + T[10] * p2 + T[11] - spel[bb * 3 + 2];
    }
}

// ============================================================================
// joints: regression partials over shifted v (float2 loads: always 8B-aligned
// since N3 even, k0*3 even)
// ============================================================================
__global__ void __launch_bounds__(256) joints_kernel(const float* __restrict__ Jreg,
                                                     const float* __restrict__ Jspin,
                                                     const float* __restrict__ Jextra,
                                                     const float* __restrict__ outv) {
    __shared__ __align__(16) float sreg[32 * 68];
    __shared__ float sv[32 * 48];
    int gb = blockIdx.x;
    int seg = blockIdx.y;
    int b0 = gb * 16;
    int tid = threadIdx.x;
    int ty = tid / 16, tx = tid % 16;
    int j0 = ty * 4;
    float acc[4][3];
#pragma unroll
    for (int i = 0; i < 4; i++)
#pragma unroll
        for (int d = 0; d < 3; d++) acc[i][d] = 0.f;

    int kbeg = seg * SEGLEN;
    for (int k0 = kbeg; k0 < kbeg + SEGLEN; k0 += 32) {
        for (int idx = tid; idx < 64 * 32; idx += 256) {
            int j = idx >> 5, vv = idx & 31;
            int gk = k0 + vv;
            float val = 0.f;
            if (j < J54 && gk < NV) {
                const float* row = reg_row(j, Jreg, Jspin, Jextra);
                val = row[gk];
            }
            sreg[vv * 68 + j] = val;
        }
        // float2 vertex loads: 16 batches x 48 float2 = 96 floats each
        for (int idx = tid; idx < 16 * 48; idx += 256) {
            int bb = idx / 48, r2 = idx % 48;
            float2 val = *(const float2*)(outv + (size_t)(b0 + bb) * N3 + k0 * 3 + r2 * 2);
            int rem = r2 * 2;
            sv[((rem + 0) / 3) * 48 + bb * 3 + (rem + 0) % 3] = val.x;
            sv[((rem + 1) / 3) * 48 + bb * 3 + (rem + 1) % 3] = val.y;
        }
        __syncthreads();
#pragma unroll
        for (int vv = 0; vv < 32; vv++) {
            float4 a = *(const float4*)&sreg[vv * 68 + j0];
            float bx = sv[vv * 48 + tx * 3 + 0];
            float by = sv[vv * 48 + tx * 3 + 1];
            float bz = sv[vv * 48 + tx * 3 + 2];
            acc[0][0] += a.x * bx; acc[0][1] += a.x * by; acc[0][2] += a.x * bz;
            acc[1][0] += a.y * bx; acc[1][1] += a.y * by; acc[1][2] += a.y * bz;
            acc[2][0] += a.z * bx; acc[2][1] += a.z * by; acc[2][2] += a.z * bz;
            acc[3][0] += a.w * bx; acc[3][1] += a.w * by; acc[3][2] += a.w * bz;
        }
        __syncthreads();
    }
    int b = b0 + tx;
#pragma unroll
    for (int i = 0; i < 4; i++) {
        int j = j0 + i;
        if (j < J54) {
#pragma unroll
            for (int d = 0; d < 3; d++)
                g_part[((size_t)(seg * BATCH + b) * J54 + j) * 3 + d] = acc[i][d];
        }
    }
}

// ============================================================================
// finalize: jall = sum partials + rowsum*pel (unshift); p2 from jall;
// write joints-p2 and p2.
// ============================================================================
__global__ void finalize_kernel(const int* __restrict__ jmap,
                                float* __restrict__ out) {
    int b = blockIdx.x, t = threadIdx.x;
    __shared__ float jall[J54 * 3];
    __shared__ float pel[3];
    int is64 = g_jmap64;
    if (t < 162) {
        int j = t / 3, d = t % 3;
        float s = g_rowsum[j] * g_pel[b * 3 + d];
        for (int seg = 0; seg < NSEG; seg++)
            s += g_part[(size_t)(seg * BATCH + b) * (J54 * 3) + t];
        jall[t] = s;
    }
    __syncthreads();
    if (t < 3) {
        int a = is64 ? jmap[2 * 27] : jmap[27];
        int c = is64 ? jmap[2 * 28] : jmap[28];
        float p = 0.5f * (jall[a * 3 + t] + jall[c * 3 + t]);
        pel[t] = p;
        out[(size_t)BATCH * N3 + (size_t)BATCH * 147 + b * 3 + t] = p;
    }
    __syncthreads();
    if (t < 147) {
        int i = t / 3, d = t % 3;
        int j = is64 ? jmap[2 * i] : jmap[i];
        out[(size_t)BATCH * N3 + b * 147 + t] = jall[j * 3 + d] - pel[d];
    }
}

// ============================================================================
extern "C" void kernel_launch(void* const* d_in, const int* in_sizes, int n_in,
                              void* d_out, int out_size) {
    const float* pose      = (const float*)d_in[0];
    const float* beta      = (const float*)d_in[1];
    const float* vtemp     = (const float*)d_in[2];
    const float* shapedirs = (const float*)d_in[3];
    const float* posedirs  = (const float*)d_in[4];
    const float* weights   = (const float*)d_in[5];
    const float* Jreg      = (const float*)d_in[6];
    const float* Jspin     = (const float*)d_in[7];
    const float* Jextra    = (const float*)d_in[8];
    const int* jmap        = (const int*)d_in[10];
    float* out = (float*)d_out;

    sniff_kernel<<<1, 32>>>(jmap);
    urow_kernel<<<27, 256>>>(Jreg, Jspin, Jextra);
    jm_kernel<<<72, 256>>>(Jreg, shapedirs, vtemp);
    pose_kernel<<<BATCH, 32>>>(pose, beta);
    pack_kernel<<<NP / 32, 256>>>(posedirs, shapedirs);
    smalls_kernel<<<J54 + NJ, 256>>>(Jreg, Jspin, Jextra, weights, vtemp);
    pelpre_kernel<<<dim3(14, NSEG), 384>>>(weights);
    pelred_kernel<<<63, 256>>>();
    pelvis_kernel<<<16, 256>>>();
    gemm_tf32_kernel<<<dim3(BATCH / 128, NP / 128), 256>>>(vtemp);
    skin_kernel<<<dim3(54, BATCH / 16), 128>>>(weights, out);
    joints_kernel<<<dim3(BATCH / 16, NSEG), 256>>>(Jreg, Jspin, Jextra, out);
    finalize_kernel<<<BATCH, 192>>>(jmap, out);
}

// round 6
// speedup vs baseline: 1.3135x; 1.3135x over previous
#include <cuda_runtime.h>
#include <cstdint>

#define BATCH 512
#define NV 6890
#define N3 20670      // NV*3
#define NP 20736      // padded N: 162*128
#define KDIM 224      // 207 + 10 + 7 pad
#define NJ 24
#define J54 54
#define NSEG 8
#define SEGLEN 864
#define KC 16

typedef unsigned long long ull;

__constant__ int c_parent[23] = {0, 0, 0, 1, 2, 3, 4, 5, 6, 7, 8, 9,
                                 9, 9, 12, 13, 14, 16, 17, 18, 19, 20, 21};

// ---- scratch ----
__device__ float g_JM[NJ * 3 * 11];
__device__ float g_Acat[BATCH * KDIM];
__device__ float g_At[KDIM * BATCH];
__device__ float g_Gc[BATCH * NJ * 12];
__device__ float g_Wt[KDIM * NP];
__device__ float g_vposed[BATCH * N3];
__device__ float g_part[NSEG * BATCH * J54 * 3];
__device__ float g_pel[BATCH * 3];
__device__ int g_jmap64;

__device__ __forceinline__ float to_tf32(float v) {
    uint32_t o;
    asm("cvt.rna.tf32.f32 %0, %1;" : "=r"(o) : "f"(v));
    return __uint_as_float(o);
}

__device__ __forceinline__ void mma_tf32(float* c, const uint32_t* a, const uint32_t* b) {
    asm volatile(
        "mma.sync.aligned.m16n8k8.row.col.f32.tf32.tf32.f32 "
        "{%0,%1,%2,%3}, {%4,%5,%6,%7}, {%8,%9}, {%0,%1,%2,%3};\n"
        : "+f"(c[0]), "+f"(c[1]), "+f"(c[2]), "+f"(c[3])
        : "r"(a[0]), "r"(a[1]), "r"(a[2]), "r"(a[3]), "r"(b[0]), "r"(b[1]));
}

// ---- packed fp32x2 (Blackwell) ----
__device__ __forceinline__ ull pk2(float x, float y) {
    ull r;
    asm("mov.b64 %0, {%1, %2};" : "=l"(r) : "f"(x), "f"(y));
    return r;
}
__device__ __forceinline__ void upk2(ull v, float& x, float& y) {
    asm("mov.b64 {%0, %1}, %2;" : "=f"(x), "=f"(y) : "l"(v));
}
__device__ __forceinline__ ull ffma2(ull a, ull b, ull c) {
    ull r;
    asm("fma.rn.f32x2 %0, %1, %2, %3;" : "=l"(r) : "l"(a), "l"(b), "l"(c));
    return r;
}

__device__ __forceinline__ const float* reg_row(int r, const float* Jreg,
                                                const float* Jspin, const float* Jextra) {
    return (r < 24) ? (Jreg + r * NV)
         : (r < 45) ? (Jspin + (r - 24) * NV)
                    : (Jextra + (r - 45) * NV);
}

// ============================================================================
__global__ void sniff_kernel(const int* __restrict__ jmap) {
    if (threadIdx.x == 0) {
        int is64 = 1;
        for (int i = 0; i < 24; i++)
            if (jmap[2 * i + 1] != 0) is64 = 0;
        g_jmap64 = is64;
    }
}

// ============================================================================
__global__ void jm_kernel(const float* __restrict__ Jreg,
                          const float* __restrict__ shapedirs,
                          const float* __restrict__ vtemp) {
    int j = blockIdx.x / 3, d = blockIdx.x % 3;
    int t = threadIdx.x;
    float acc[11];
#pragma unroll
    for (int k = 0; k < 11; k++) acc[k] = 0.f;
    const float* reg = Jreg + j * NV;
    for (int v = t; v < NV; v += 256) {
        float r = reg[v];
        const float* sd = shapedirs + (v * 3 + d) * 10;
#pragma unroll
        for (int k = 0; k < 10; k++) acc[k] += r * sd[k];
        acc[10] += r * vtemp[v * 3 + d];
    }
    __shared__ float red[256];
    for (int k = 0; k < 11; k++) {
        red[t] = acc[k];
        __syncthreads();
        for (int s = 128; s > 0; s >>= 1) {
            if (t < s) red[t] += red[t + s];
            __syncthreads();
        }
        if (t == 0) g_JM[(j * 3 + d) * 11 + k] = red[0];
        __syncthreads();
    }
}

// ============================================================================
// pose: 4 batches per block (one warp each); rodrigues, chain, Gc, At
// ============================================================================
__global__ void __launch_bounds__(128) pose_kernel(const float* __restrict__ pose,
                                                   const float* __restrict__ beta) {
    int w = threadIdx.x >> 5, t = threadIdx.x & 31;
    int b = blockIdx.x * 4 + w;
    __shared__ float sR[4][NJ][9];
    __shared__ float sJ[4][NJ][3];
    __shared__ float sA[4][NJ][12];

    if (t < NJ) {
        float rx = pose[b * 72 + 3 * t + 0];
        float ry = pose[b * 72 + 3 * t + 1];
        float rz = pose[b * 72 + 3 * t + 2];
        float th = sqrtf(rx * rx + ry * ry + rz * rz);
        float inv = 1.f / fmaxf(th, 1e-8f);
        float kx = rx * inv, ky = ry * inv, kz = rz * inv;
        float s = sinf(th), c = cosf(th), C = 1.f - c;
        float kn2 = kx * kx + ky * ky + kz * kz;
        float R[9];
        R[0] = 1.f + C * (kx * kx - kn2);
        R[1] = -s * kz + C * kx * ky;
        R[2] = s * ky + C * kx * kz;
        R[3] = s * kz + C * ky * kx;
        R[4] = 1.f + C * (ky * ky - kn2);
        R[5] = -s * kx + C * ky * kz;
        R[6] = -s * ky + C * kz * kx;
        R[7] = s * kx + C * kz * ky;
        R[8] = 1.f + C * (kz * kz - kn2);
#pragma unroll
        for (int e = 0; e < 9; e++) sR[w][t][e] = R[e];
        if (t >= 1) {
            float* dst = g_Acat + b * KDIM + (t - 1) * 9;
#pragma unroll
            for (int e = 0; e < 9; e++) {
                float val = R[e] - ((e == 0 || e == 4 || e == 8) ? 1.f : 0.f);
                dst[e] = val;
                g_At[((t - 1) * 9 + e) * BATCH + b] = to_tf32(val);
            }
        }
#pragma unroll
        for (int d = 0; d < 3; d++) {
            const float* m = g_JM + (t * 3 + d) * 11;
            float val = m[10];
#pragma unroll
            for (int k = 0; k < 10; k++) val += m[k] * beta[b * 10 + k];
            sJ[w][t][d] = val;
        }
    }
    if (t == 0) {
#pragma unroll
        for (int k = 0; k < 10; k++) {
            float bv = beta[b * 10 + k];
            g_Acat[b * KDIM + 207 + k] = bv;
            g_At[(207 + k) * BATCH + b] = to_tf32(bv);
        }
#pragma unroll
        for (int k = 217; k < KDIM; k++) {
            g_Acat[b * KDIM + k] = 0.f;
            g_At[k * BATCH + b] = 0.f;
        }
    }
    __syncwarp();
    if (t == 0) {
#pragma unroll
        for (int e = 0; e < 9; e++) sA[w][0][(e / 3) * 4 + (e % 3)] = sR[w][0][e];
        sA[w][0][3] = sJ[w][0][0]; sA[w][0][7] = sJ[w][0][1]; sA[w][0][11] = sJ[w][0][2];
        for (int i = 1; i < NJ; i++) {
            int p = c_parent[i - 1];
            float lt0 = sJ[w][i][0] - sJ[w][p][0];
            float lt1 = sJ[w][i][1] - sJ[w][p][1];
            float lt2 = sJ[w][i][2] - sJ[w][p][2];
            for (int r = 0; r < 3; r++) {
                float p0 = sA[w][p][r * 4 + 0], p1 = sA[w][p][r * 4 + 1];
                float p2 = sA[w][p][r * 4 + 2], p3 = sA[w][p][r * 4 + 3];
                for (int cc = 0; cc < 3; cc++)
                    sA[w][i][r * 4 + cc] = p0 * sR[w][i][0 * 3 + cc] + p1 * sR[w][i][1 * 3 + cc] + p2 * sR[w][i][2 * 3 + cc];
                sA[w][i][r * 4 + 3] = p0 * lt0 + p1 * lt1 + p2 * lt2 + p3;
            }
        }
    }
    __syncwarp();
    if (t < NJ) {
        float j0 = sJ[w][t][0], j1 = sJ[w][t][1], j2 = sJ[w][t][2];
        float* dst = g_Gc + (b * NJ + t) * 12;
#pragma unroll
        for (int r = 0; r < 3; r++) {
            float a0 = sA[w][t][r * 4 + 0], a1 = sA[w][t][r * 4 + 1];
            float a2 = sA[w][t][r * 4 + 2], a3 = sA[w][t][r * 4 + 3];
            dst[r * 4 + 0] = a0; dst[r * 4 + 1] = a1; dst[r * 4 + 2] = a2;
            dst[r * 4 + 3] = a3 - (a0 * j0 + a1 * j1 + a2 * j2);
        }
    }
}

// ============================================================================
__global__ void pack_kernel(const float* __restrict__ posedirs,
                            const float* __restrict__ shapedirs) {
    __shared__ float s[32 * 225];
    int n0 = blockIdx.x * 32;
    int t = threadIdx.x;
    for (int idx = t; idx < 32 * 207; idx += 256) {
        int n = idx / 207, k = idx % 207;
        int gn = n0 + n;
        s[n * 225 + k] = (gn < N3) ? posedirs[gn * 207 + k] : 0.f;
    }
    for (int idx = t; idx < 32 * 10; idx += 256) {
        int n = idx / 10, k = idx % 10;
        int gn = n0 + n;
        s[n * 225 + 207 + k] = (gn < N3) ? shapedirs[gn * 10 + k] : 0.f;
    }
    for (int idx = t; idx < 32 * 7; idx += 256) {
        int n = idx / 7, k = idx % 7;
        s[n * 225 + 217 + k] = 0.f;
    }
    __syncthreads();
    for (int idx = t; idx < KDIM * 32; idx += 256) {
        int k = idx / 32, n = idx % 32;
        g_Wt[k * NP + n0 + n] = to_tf32(s[n * 225 + k]);
    }
}

// ============================================================================
// GEMM TF32: v_posed = At^T @ Wt + vtemp
// ============================================================================
__global__ void __launch_bounds__(256, 2) gemm_tf32_kernel(const float* __restrict__ vtemp) {
    __shared__ __align__(16) float As[2][KC][132];
    __shared__ __align__(16) float Bs[2][KC][132];
    int tid = threadIdx.x;
    int lane = tid & 31, wid = tid >> 5;
    int warp_m = wid & 1, warp_n = wid >> 1;
    int gq = lane >> 2, tq = lane & 3;
    int m0 = blockIdx.x * 128;
    int n0 = blockIdx.y * 128;

    float acc[4][4][4];
#pragma unroll
    for (int mt = 0; mt < 4; mt++)
#pragma unroll
        for (int nt = 0; nt < 4; nt++)
#pragma unroll
            for (int i = 0; i < 4; i++) acc[mt][nt][i] = 0.f;

    const int NSTAGE = KDIM / KC;

#define LOAD_STAGE(s, buf)                                                          \
    {                                                                               \
        int k0 = (s) * KC;                                                          \
        _Pragma("unroll")                                                           \
        for (int i = 0; i < 2; i++) {                                               \
            int idx = tid + i * 256;                                                \
            int k = idx >> 5, mg = (idx & 31) << 2;                                 \
            unsigned da = (unsigned)__cvta_generic_to_shared(&As[buf][k][mg]);      \
            const float* sa = g_At + (k0 + k) * BATCH + m0 + mg;                    \
            asm volatile("cp.async.cg.shared.global [%0], [%1], 16;" ::"r"(da), "l"(sa)); \
            unsigned db = (unsigned)__cvta_generic_to_shared(&Bs[buf][k][mg]);      \
            const float* sb = g_Wt + (size_t)(k0 + k) * NP + n0 + mg;               \
            asm volatile("cp.async.cg.shared.global [%0], [%1], 16;" ::"r"(db), "l"(sb)); \
        }                                                                           \
        asm volatile("cp.async.commit_group;");                                     \
    }

    LOAD_STAGE(0, 0);
    for (int s = 0; s < NSTAGE; s++) {
        int buf = s & 1;
        if (s + 1 < NSTAGE) {
            LOAD_STAGE(s + 1, buf ^ 1);
            asm volatile("cp.async.wait_group 1;");
        } else {
            asm volatile("cp.async.wait_group 0;");
        }
        __syncthreads();
#pragma unroll
        for (int kk = 0; kk < KC / 8; kk++) {
            int kb = kk * 8;
            uint32_t af[4][4], bf[4][2];
#pragma unroll
            for (int mt = 0; mt < 4; mt++) {
                int r = warp_m * 64 + mt * 16 + gq;
                af[mt][0] = __float_as_uint(As[buf][kb + tq][r]);
                af[mt][1] = __float_as_uint(As[buf][kb + tq][r + 8]);
                af[mt][2] = __float_as_uint(As[buf][kb + tq + 4][r]);
                af[mt][3] = __float_as_uint(As[buf][kb + tq + 4][r + 8]);
            }
#pragma unroll
            for (int nt = 0; nt < 4; nt++) {
                int cn = warp_n * 32 + nt * 8 + gq;
                bf[nt][0] = __float_as_uint(Bs[buf][kb + tq][cn]);
                bf[nt][1] = __float_as_uint(Bs[buf][kb + tq + 4][cn]);
            }
#pragma unroll
            for (int mt = 0; mt < 4; mt++)
#pragma unroll
                for (int nt = 0; nt < 4; nt++)
                    mma_tf32(acc[mt][nt], af[mt], bf[nt]);
        }
        __syncthreads();
    }

#pragma unroll
    for (int mt = 0; mt < 4; mt++) {
        int row = m0 + warp_m * 64 + mt * 16 + gq;
#pragma unroll
        for (int nt = 0; nt < 4; nt++) {
            int cn = n0 + warp_n * 32 + nt * 8 + 2 * tq;
            if (cn < N3) {
                float2 vt = *(const float2*)(vtemp + cn);
                float2 o0 = {acc[mt][nt][0] + vt.x, acc[mt][nt][1] + vt.y};
                float2 o1 = {acc[mt][nt][2] + vt.x, acc[mt][nt][3] + vt.y};
                *(float2*)(g_vposed + (size_t)row * N3 + cn) = o0;
                *(float2*)(g_vposed + (size_t)(row + 8) * N3 + cn) = o1;
            }
        }
    }
#undef LOAD_STAGE
}

// ============================================================================
// skin: 128 verts x 16 batches (8 packed pairs) per block, fp32x2 FMA
// ============================================================================
__global__ void __launch_bounds__(128) skin_kernel(const float* __restrict__ weights,
                                                   float* __restrict__ out) {
    __shared__ __align__(16) ull sGc2[8 * 288];   // [pair][j*12+c] packed (b_even, b_odd)
    int b0 = blockIdx.y * 16;
    int v = blockIdx.x * 128 + threadIdx.x;
    for (int idx = threadIdx.x; idx < 8 * 288; idx += 128) {
        int p = idx / 288, e = idx % 288;
        sGc2[idx] = pk2(g_Gc[(size_t)(b0 + 2 * p) * 288 + e],
                        g_Gc[(size_t)(b0 + 2 * p + 1) * 288 + e]);
    }
    __syncthreads();
    if (v >= NV) return;
    float w[NJ];
#pragma unroll
    for (int j = 0; j < NJ; j++) w[j] = weights[v * NJ + j];
#pragma unroll 1
    for (int p = 0; p < 8; p++) {
        ull T2[12];
#pragma unroll
        for (int c = 0; c < 12; c++) T2[c] = 0ull;
        const ulonglong2* gc = (const ulonglong2*)(sGc2 + p * 288);
#pragma unroll
        for (int j = 0; j < NJ; j++) {
            ull wj2 = pk2(w[j], w[j]);
#pragma unroll
            for (int i = 0; i < 6; i++) {
                ulonglong2 g2 = gc[j * 6 + i];
                T2[2 * i + 0] = ffma2(wj2, g2.x, T2[2 * i + 0]);
                T2[2 * i + 1] = ffma2(wj2, g2.y, T2[2 * i + 1]);
            }
        }
        const float* vpa = g_vposed + (size_t)(b0 + 2 * p) * N3 + v * 3;
        const float* vpb = g_vposed + (size_t)(b0 + 2 * p + 1) * N3 + v * 3;
        ull px = pk2(vpa[0], vpb[0]);
        ull py = pk2(vpa[1], vpb[1]);
        ull pz = pk2(vpa[2], vpb[2]);
        float* oa = out + (size_t)(b0 + 2 * p) * N3 + v * 3;
        float* ob = out + (size_t)(b0 + 2 * p + 1) * N3 + v * 3;
#pragma unroll
        for (int r = 0; r < 3; r++) {
            ull o2 = ffma2(T2[4 * r + 0], px,
                     ffma2(T2[4 * r + 1], py,
                     ffma2(T2[4 * r + 2], pz, T2[4 * r + 3])));
            float xa, xb;
            upk2(o2, xa, xb);
            oa[r] = xa;
            ob[r] = xb;
        }
    }
}

// ============================================================================
// joints: 32 batches/block (16 packed pairs), fp32x2 accumulate
// ============================================================================
__global__ void __launch_bounds__(256) joints_kernel(const float* __restrict__ Jreg,
                                                     const float* __restrict__ Jspin,
                                                     const float* __restrict__ Jextra,
                                                     const float* __restrict__ outv) {
    __shared__ __align__(16) float sreg[32 * 68];
    __shared__ __align__(16) ull sv2[32 * 48];    // [vv][pair*3+d] packed
    float* svh = (float*)sv2;
    int b0 = blockIdx.x * 32;   // grid.x = 16
    int seg = blockIdx.y;
    int tid = threadIdx.x;
    int ty = tid / 16, tx = tid % 16;  // ty -> 4 joints, tx -> batch pair
    int j0 = ty * 4;
    ull acc2[4][3];
#pragma unroll
    for (int i = 0; i < 4; i++)
#pragma unroll
        for (int d = 0; d < 3; d++) acc2[i][d] = 0ull;

    int kbeg = seg * SEGLEN;
    for (int k0 = kbeg; k0 < kbeg + SEGLEN; k0 += 32) {
        for (int idx = tid; idx < 64 * 32; idx += 256) {
            int j = idx >> 5, vv = idx & 31;
            int gk = k0 + vv;
            float val = 0.f;
            if (j < J54 && gk < NV) {
                const float* row = reg_row(j, Jreg, Jspin, Jextra);
                val = row[gk];
            }
            sreg[vv * 68 + j] = val;
        }
        // fill sv2: 32 batches x 48 float2 loads (8B-aligned: N3 even, k0*3 even)
        for (int idx = tid; idx < 32 * 48; idx += 256) {
            int bb = idx / 48, r2 = idx % 48;
            float2 val = *(const float2*)(outv + (size_t)(b0 + bb) * N3 + k0 * 3 + r2 * 2);
            int rem = r2 * 2;
            int f0 = rem / 3, d0 = rem % 3;
            int f1 = (rem + 1) / 3, d1 = (rem + 1) % 3;
            int half = bb & 1, pr = bb >> 1;
            svh[(f0 * 48 + pr * 3 + d0) * 2 + half] = val.x;
            svh[(f1 * 48 + pr * 3 + d1) * 2 + half] = val.y;
        }
        __syncthreads();
#pragma unroll
        for (int vv = 0; vv < 32; vv++) {
            float4 a = *(const float4*)&sreg[vv * 68 + j0];
            ull ax = pk2(a.x, a.x), ay = pk2(a.y, a.y);
            ull az = pk2(a.z, a.z), aw = pk2(a.w, a.w);
            ull bx = sv2[vv * 48 + tx * 3 + 0];
            ull by = sv2[vv * 48 + tx * 3 + 1];
            ull bz = sv2[vv * 48 + tx * 3 + 2];
            acc2[0][0] = ffma2(ax, bx, acc2[0][0]);
            acc2[0][1] = ffma2(ax, by, acc2[0][1]);
            acc2[0][2] = ffma2(ax, bz, acc2[0][2]);
            acc2[1][0] = ffma2(ay, bx, acc2[1][0]);
            acc2[1][1] = ffma2(ay, by, acc2[1][1]);
            acc2[1][2] = ffma2(ay, bz, acc2[1][2]);
            acc2[2][0] = ffma2(az, bx, acc2[2][0]);
            acc2[2][1] = ffma2(az, by, acc2[2][1]);
            acc2[2][2] = ffma2(az, bz, acc2[2][2]);
            acc2[3][0] = ffma2(aw, bx, acc2[3][0]);
            acc2[3][1] = ffma2(aw, by, acc2[3][1]);
            acc2[3][2] = ffma2(aw, bz, acc2[3][2]);
        }
        __syncthreads();
    }
    int ba = b0 + 2 * tx, bb2 = ba + 1;
#pragma unroll
    for (int i = 0; i < 4; i++) {
        int j = j0 + i;
        if (j < J54) {
#pragma unroll
            for (int d = 0; d < 3; d++) {
                float xa, xb;
                upk2(acc2[i][d], xa, xb);
                g_part[((size_t)(seg * BATCH + ba) * J54 + j) * 3 + d] = xa;
                g_part[((size_t)(seg * BATCH + bb2) * J54 + j) * 3 + d] = xb;
            }
        }
    }
}

// ============================================================================
// finalize: sum partials, pelvis, write joints & pelvis, record g_pel
// ============================================================================
__global__ void finalize_kernel(const int* __restrict__ jmap,
                                float* __restrict__ out) {
    int b = blockIdx.x, t = threadIdx.x;
    __shared__ float jall[J54 * 3];
    __shared__ float pel[3];
    int is64 = g_jmap64;
    if (t < 162) {
        float s = 0.f;
        for (int seg = 0; seg < NSEG; seg++)
            s += g_part[(size_t)(seg * BATCH + b) * (J54 * 3) + t];
        jall[t] = s;
    }
    __syncthreads();
    if (t < 3) {
        int a = is64 ? jmap[2 * 27] : jmap[27];
        int c = is64 ? jmap[2 * 28] : jmap[28];
        float p = 0.5f * (jall[a * 3 + t] + jall[c * 3 + t]);
        pel[t] = p;
        g_pel[b * 3 + t] = p;
        out[(size_t)BATCH * N3 + (size_t)BATCH * 147 + b * 3 + t] = p;
    }
    __syncthreads();
    if (t < 147) {
        int i = t / 3, d = t % 3;
        int j = is64 ? jmap[2 * i] : jmap[i];
        out[(size_t)BATCH * N3 + b * 147 + t] = jall[j * 3 + d] - pel[d];
    }
}

// ============================================================================
// subv: v -= pelvis, float2 (N3 even => never straddles a batch row)
// ============================================================================
__global__ void subv_kernel(float* __restrict__ out) {
    int gi = blockIdx.x * 256 + threadIdx.x;
    int idx = gi * 2;
    if (idx < BATCH * N3) {
        int b = idx / N3;
        int r = idx % N3;
        int d0 = r % 3;
        int d1 = d0 + 1; if (d1 == 3) d1 = 0;
        float2 v = *(float2*)(out + idx);
        v.x -= g_pel[b * 3 + d0];
        v.y -= g_pel[b * 3 + d1];
        *(float2*)(out + idx) = v;
    }
}

// ============================================================================
extern "C" void kernel_launch(void* const* d_in, const int* in_sizes, int n_in,
                              void* d_out, int out_size) {
    const float* pose      = (const float*)d_in[0];
    const float* beta      = (const float*)d_in[1];
    const float* vtemp     = (const float*)d_in[2];
    const float* shapedirs = (const float*)d_in[3];
    const float* posedirs  = (const float*)d_in[4];
    const float* weights   = (const float*)d_in[5];
    const float* Jreg      = (const float*)d_in[6];
    const float* Jspin     = (const float*)d_in[7];
    const float* Jextra    = (const float*)d_in[8];
    const int* jmap        = (const int*)d_in[10];
    float* out = (float*)d_out;

    sniff_kernel<<<1, 32>>>(jmap);
    jm_kernel<<<72, 256>>>(Jreg, shapedirs, vtemp);
    pose_kernel<<<BATCH / 4, 128>>>(pose, beta);
    pack_kernel<<<NP / 32, 256>>>(posedirs, shapedirs);
    gemm_tf32_kernel<<<dim3(BATCH / 128, NP / 128), 256>>>(vtemp);
    skin_kernel<<<dim3(54, BATCH / 16), 128>>>(weights, out);
    joints_kernel<<<dim3(BATCH / 32, NSEG), 256>>>(Jreg, Jspin, Jextra, out);
    finalize_kernel<<<BATCH, 192>>>(jmap, out);
    subv_kernel<<<(BATCH * N3 / 2 + 255) / 256, 256>>>(out);
}

// round 7
// speedup vs baseline: 1.3906x; 1.0586x over previous
#include <cuda_runtime.h>
#include <cuda_bf16.h>
#include <cstdint>

#define BATCH 512
#define NV 6890
#define N3 20670      // NV*3
#define NP 20736      // padded N: 162*128
#define KDIM 224      // 207 + 10 + 7 pad
#define NJ 24
#define J54 54
#define NSEG 8
#define SEGLEN 864

typedef unsigned long long ull;

__constant__ int c_parent[23] = {0, 0, 0, 1, 2, 3, 4, 5, 6, 7, 8, 9,
                                 9, 9, 12, 13, 14, 16, 17, 18, 19, 20, 21};

// ---- scratch ----
__device__ float g_JM[NJ * 3 * 11];
__device__ __nv_bfloat16 g_Ab[BATCH * KDIM];   // A row-major [b][k] bf16
__device__ __nv_bfloat16 g_Wb[(size_t)NP * KDIM]; // W row-major [n][k] bf16
__device__ float g_Gc[BATCH * NJ * 12];
__device__ float g_vposed[BATCH * N3];
__device__ float g_part[NSEG * BATCH * J54 * 3];
__device__ int g_jmap64;

__device__ __forceinline__ void mma_bf16(float* c, const uint32_t* a, const uint32_t* b) {
    asm volatile(
        "mma.sync.aligned.m16n8k16.row.col.f32.bf16.bf16.f32 "
        "{%0,%1,%2,%3}, {%4,%5,%6,%7}, {%8,%9}, {%0,%1,%2,%3};\n"
        : "+f"(c[0]), "+f"(c[1]), "+f"(c[2]), "+f"(c[3])
        : "r"(a[0]), "r"(a[1]), "r"(a[2]), "r"(a[3]), "r"(b[0]), "r"(b[1]));
}

// ---- packed fp32x2 ----
__device__ __forceinline__ ull pk2(float x, float y) {
    ull r;
    asm("mov.b64 %0, {%1, %2};" : "=l"(r) : "f"(x), "f"(y));
    return r;
}
__device__ __forceinline__ void upk2(ull v, float& x, float& y) {
    asm("mov.b64 {%0, %1}, %2;" : "=f"(x), "=f"(y) : "l"(v));
}
__device__ __forceinline__ ull ffma2(ull a, ull b, ull c) {
    ull r;
    asm("fma.rn.f32x2 %0, %1, %2, %3;" : "=l"(r) : "l"(a), "l"(b), "l"(c));
    return r;
}

__device__ __forceinline__ const float* reg_row(int r, const float* Jreg,
                                                const float* Jspin, const float* Jextra) {
    return (r < 24) ? (Jreg + r * NV)
         : (r < 45) ? (Jspin + (r - 24) * NV)
                    : (Jextra + (r - 45) * NV);
}

// ============================================================================
// pack: W row-major [n][k] bf16 (pure streaming convert, no transpose)
// ============================================================================
__global__ void __launch_bounds__(224) pack_kernel(const float* __restrict__ posedirs,
                                                   const float* __restrict__ shapedirs) {
    int n0 = blockIdx.x * 8;
    int t = threadIdx.x;   // 0..223
#pragma unroll
    for (int r = 0; r < 8; r++) {
        int n = n0 + r;
        float v = 0.f;
        if (n < N3) {
            if (t < 207)      v = posedirs[(size_t)n * 207 + t];
            else if (t < 217) v = shapedirs[n * 10 + (t - 207)];
        }
        g_Wb[(size_t)n * KDIM + t] = __float2bfloat16(v);
    }
}

// ============================================================================
__global__ void jm_kernel(const float* __restrict__ Jreg,
                          const float* __restrict__ shapedirs,
                          const float* __restrict__ vtemp) {
    int j = blockIdx.x / 3, d = blockIdx.x % 3;
    int t = threadIdx.x;
    float acc[11];
#pragma unroll
    for (int k = 0; k < 11; k++) acc[k] = 0.f;
    const float* reg = Jreg + j * NV;
    for (int v = t; v < NV; v += 256) {
        float r = reg[v];
        const float* sd = shapedirs + (v * 3 + d) * 10;
#pragma unroll
        for (int k = 0; k < 10; k++) acc[k] += r * sd[k];
        acc[10] += r * vtemp[v * 3 + d];
    }
    __shared__ float red[256];
    for (int k = 0; k < 11; k++) {
        red[t] = acc[k];
        __syncthreads();
        for (int s = 128; s > 0; s >>= 1) {
            if (t < s) red[t] += red[t + s];
            __syncthreads();
        }
        if (t == 0) g_JM[(j * 3 + d) * 11 + k] = red[0];
        __syncthreads();
    }
}

// ============================================================================
// pose: 4 batches per block; rodrigues, chain, Gc; writes bf16 A rows
// ============================================================================
__global__ void __launch_bounds__(128) pose_kernel(const float* __restrict__ pose,
                                                   const float* __restrict__ beta) {
    int w = threadIdx.x >> 5, t = threadIdx.x & 31;
    int b = blockIdx.x * 4 + w;
    __shared__ float sR[4][NJ][9];
    __shared__ float sJ[4][NJ][3];
    __shared__ float sA[4][NJ][12];

    if (t < NJ) {
        float rx = pose[b * 72 + 3 * t + 0];
        float ry = pose[b * 72 + 3 * t + 1];
        float rz = pose[b * 72 + 3 * t + 2];
        float th = sqrtf(rx * rx + ry * ry + rz * rz);
        float inv = 1.f / fmaxf(th, 1e-8f);
        float kx = rx * inv, ky = ry * inv, kz = rz * inv;
        float s = sinf(th), c = cosf(th), C = 1.f - c;
        float kn2 = kx * kx + ky * ky + kz * kz;
        float R[9];
        R[0] = 1.f + C * (kx * kx - kn2);
        R[1] = -s * kz + C * kx * ky;
        R[2] = s * ky + C * kx * kz;
        R[3] = s * kz + C * ky * kx;
        R[4] = 1.f + C * (ky * ky - kn2);
        R[5] = -s * kx + C * ky * kz;
        R[6] = -s * ky + C * kz * kx;
        R[7] = s * kx + C * kz * ky;
        R[8] = 1.f + C * (kz * kz - kn2);
#pragma unroll
        for (int e = 0; e < 9; e++) sR[w][t][e] = R[e];
        if (t >= 1) {
            __nv_bfloat16* dst = g_Ab + b * KDIM + (t - 1) * 9;
#pragma unroll
            for (int e = 0; e < 9; e++) {
                float val = R[e] - ((e == 0 || e == 4 || e == 8) ? 1.f : 0.f);
                dst[e] = __float2bfloat16(val);
            }
        }
#pragma unroll
        for (int d = 0; d < 3; d++) {
            const float* m = g_JM + (t * 3 + d) * 11;
            float val = m[10];
#pragma unroll
            for (int k = 0; k < 10; k++) val += m[k] * beta[b * 10 + k];
            sJ[w][t][d] = val;
        }
    }
    if (t == 0) {
#pragma unroll
        for (int k = 0; k < 10; k++)
            g_Ab[b * KDIM + 207 + k] = __float2bfloat16(beta[b * 10 + k]);
#pragma unroll
        for (int k = 217; k < KDIM; k++)
            g_Ab[b * KDIM + k] = __float2bfloat16(0.f);
    }
    __syncwarp();
    if (t == 0) {
#pragma unroll
        for (int e = 0; e < 9; e++) sA[w][0][(e / 3) * 4 + (e % 3)] = sR[w][0][e];
        sA[w][0][3] = sJ[w][0][0]; sA[w][0][7] = sJ[w][0][1]; sA[w][0][11] = sJ[w][0][2];
        for (int i = 1; i < NJ; i++) {
            int p = c_parent[i - 1];
            float lt0 = sJ[w][i][0] - sJ[w][p][0];
            float lt1 = sJ[w][i][1] - sJ[w][p][1];
            float lt2 = sJ[w][i][2] - sJ[w][p][2];
            for (int r = 0; r < 3; r++) {
                float p0 = sA[w][p][r * 4 + 0], p1 = sA[w][p][r * 4 + 1];
                float p2 = sA[w][p][r * 4 + 2], p3 = sA[w][p][r * 4 + 3];
                for (int cc = 0; cc < 3; cc++)
                    sA[w][i][r * 4 + cc] = p0 * sR[w][i][0 * 3 + cc] + p1 * sR[w][i][1 * 3 + cc] + p2 * sR[w][i][2 * 3 + cc];
                sA[w][i][r * 4 + 3] = p0 * lt0 + p1 * lt1 + p2 * lt2 + p3;
            }
        }
    }
    __syncwarp();
    if (t < NJ) {
        float j0 = sJ[w][t][0], j1 = sJ[w][t][1], j2 = sJ[w][t][2];
        float* dst = g_Gc + (b * NJ + t) * 12;
#pragma unroll
        for (int r = 0; r < 3; r++) {
            float a0 = sA[w][t][r * 4 + 0], a1 = sA[w][t][r * 4 + 1];
            float a2 = sA[w][t][r * 4 + 2], a3 = sA[w][t][r * 4 + 3];
            dst[r * 4 + 0] = a0; dst[r * 4 + 1] = a1; dst[r * 4 + 2] = a2;
            dst[r * 4 + 3] = a3 - (a0 * j0 + a1 * j1 + a2 * j2);
        }
    }
}

// ============================================================================
// GEMM bf16 m16n8k16: v_posed = A @ W^T + vtemp
// Block 128x128, 8 warps (2x4), K-chunk 16, cp.async double buffer.
// smem rows padded to 24 halfs (48B) -> conflict-free u32 fragment loads.
// ============================================================================
__global__ void __launch_bounds__(256, 2) gemm_bf16_kernel(const float* __restrict__ vtemp) {
    __shared__ __align__(16) __nv_bfloat16 As[2][128][24];
    __shared__ __align__(16) __nv_bfloat16 Bs[2][128][24];
    int tid = threadIdx.x;
    int lane = tid & 31, wid = tid >> 5;
    int warp_m = wid & 1, warp_n = wid >> 1;
    int gq = lane >> 2, tq = lane & 3;
    int m0 = blockIdx.x * 128;
    int n0 = blockIdx.y * 128;

    float acc[4][4][4];
#pragma unroll
    for (int mt = 0; mt < 4; mt++)
#pragma unroll
        for (int nt = 0; nt < 4; nt++)
#pragma unroll
            for (int i = 0; i < 4; i++) acc[mt][nt][i] = 0.f;

    const int NSTAGE = KDIM / 16;  // 14
    const int mrow = tid >> 1, hh = tid & 1;

#define LOAD_STAGE(s, buf)                                                            \
    {                                                                                 \
        int k0 = (s) * 16;                                                            \
        unsigned da = (unsigned)__cvta_generic_to_shared(&As[buf][mrow][hh * 8]);     \
        const __nv_bfloat16* sa = g_Ab + (m0 + mrow) * KDIM + k0 + hh * 8;            \
        asm volatile("cp.async.cg.shared.global [%0], [%1], 16;" ::"r"(da), "l"(sa)); \
        unsigned db = (unsigned)__cvta_generic_to_shared(&Bs[buf][mrow][hh * 8]);     \
        const __nv_bfloat16* sb = g_Wb + (size_t)(n0 + mrow) * KDIM + k0 + hh * 8;    \
        asm volatile("cp.async.cg.shared.global [%0], [%1], 16;" ::"r"(db), "l"(sb)); \
        asm volatile("cp.async.commit_group;");                                       \
    }

    LOAD_STAGE(0, 0);
    for (int s = 0; s < NSTAGE; s++) {
        int buf = s & 1;
        if (s + 1 < NSTAGE) {
            LOAD_STAGE(s + 1, buf ^ 1);
            asm volatile("cp.async.wait_group 1;");
        } else {
            asm volatile("cp.async.wait_group 0;");
        }
        __syncthreads();
        const uint32_t* As32 = (const uint32_t*)&As[buf][0][0];
        const uint32_t* Bs32 = (const uint32_t*)&Bs[buf][0][0];
        uint32_t af[4][4], bf[4][2];
#pragma unroll
        for (int mt = 0; mt < 4; mt++) {
            int r = warp_m * 64 + mt * 16 + gq;
            af[mt][0] = As32[r * 12 + tq];
            af[mt][1] = As32[(r + 8) * 12 + tq];
            af[mt][2] = As32[r * 12 + 4 + tq];
            af[mt][3] = As32[(r + 8) * 12 + 4 + tq];
        }
#pragma unroll
        for (int nt = 0; nt < 4; nt++) {
            int cn = warp_n * 32 + nt * 8 + gq;
            bf[nt][0] = Bs32[cn * 12 + tq];
            bf[nt][1] = Bs32[cn * 12 + 4 + tq];
        }
#pragma unroll
        for (int mt = 0; mt < 4; mt++)
#pragma unroll
            for (int nt = 0; nt < 4; nt++)
                mma_bf16(acc[mt][nt], af[mt], bf[nt]);
        __syncthreads();
    }

#pragma unroll
    for (int mt = 0; mt < 4; mt++) {
        int row = m0 + warp_m * 64 + mt * 16 + gq;
#pragma unroll
        for (int nt = 0; nt < 4; nt++) {
            int cn = n0 + warp_n * 32 + nt * 8 + 2 * tq;
            if (cn < N3) {
                float2 vt = *(const float2*)(vtemp + cn);
                float2 o0 = {acc[mt][nt][0] + vt.x, acc[mt][nt][1] + vt.y};
                float2 o1 = {acc[mt][nt][2] + vt.x, acc[mt][nt][3] + vt.y};
                *(float2*)(g_vposed + (size_t)row * N3 + cn) = o0;
                *(float2*)(g_vposed + (size_t)(row + 8) * N3 + cn) = o1;
            }
        }
    }
#undef LOAD_STAGE
}

// ============================================================================
__global__ void sniff_kernel(const int* __restrict__ jmap) {
    int t = threadIdx.x;
    int bad = (t < 24 && jmap[2 * t + 1] != 0) ? 1 : 0;
    unsigned m = __ballot_sync(0xffffffff, bad);
    if (t == 0) g_jmap64 = (m == 0) ? 1 : 0;
}

// ============================================================================
// skin: 128 verts x 16 batches (8 packed pairs) per block, fp32x2 FMA
// ============================================================================
__global__ void __launch_bounds__(128) skin_kernel(const float* __restrict__ weights,
                                                   float* __restrict__ out) {
    __shared__ __align__(16) ull sGc2[8 * 288];
    int b0 = blockIdx.y * 16;
    int v = blockIdx.x * 128 + threadIdx.x;
    for (int idx = threadIdx.x; idx < 8 * 288; idx += 128) {
        int p = idx / 288, e = idx % 288;
        sGc2[idx] = pk2(g_Gc[(size_t)(b0 + 2 * p) * 288 + e],
                        g_Gc[(size_t)(b0 + 2 * p + 1) * 288 + e]);
    }
    __syncthreads();
    if (v >= NV) return;
    float w[NJ];
#pragma unroll
    for (int j = 0; j < NJ; j++) w[j] = weights[v * NJ + j];
#pragma unroll 1
    for (int p = 0; p < 8; p++) {
        ull T2[12];
#pragma unroll
        for (int c = 0; c < 12; c++) T2[c] = 0ull;
        const ulonglong2* gc = (const ulonglong2*)(sGc2 + p * 288);
#pragma unroll
        for (int j = 0; j < NJ; j++) {
            ull wj2 = pk2(w[j], w[j]);
#pragma unroll
            for (int i = 0; i < 6; i++) {
                ulonglong2 g2 = gc[j * 6 + i];
                T2[2 * i + 0] = ffma2(wj2, g2.x, T2[2 * i + 0]);
                T2[2 * i + 1] = ffma2(wj2, g2.y, T2[2 * i + 1]);
            }
        }
        const float* vpa = g_vposed + (size_t)(b0 + 2 * p) * N3 + v * 3;
        const float* vpb = g_vposed + (size_t)(b0 + 2 * p + 1) * N3 + v * 3;
        ull px = pk2(vpa[0], vpb[0]);
        ull py = pk2(vpa[1], vpb[1]);
        ull pz = pk2(vpa[2], vpb[2]);
        float* oa = out + (size_t)(b0 + 2 * p) * N3 + v * 3;
        float* ob = out + (size_t)(b0 + 2 * p + 1) * N3 + v * 3;
#pragma unroll
        for (int r = 0; r < 3; r++) {
            ull o2 = ffma2(T2[4 * r + 0], px,
                     ffma2(T2[4 * r + 1], py,
                     ffma2(T2[4 * r + 2], pz, T2[4 * r + 3])));
            float xa, xb;
            upk2(o2, xa, xb);
            oa[r] = xa;
            ob[r] = xb;
        }
    }
}

// ============================================================================
// joints: 32 batches/block (16 packed pairs), fp32x2 accumulate
// ============================================================================
__global__ void __launch_bounds__(256) joints_kernel(const float* __restrict__ Jreg,
                                                     const float* __restrict__ Jspin,
                                                     const float* __restrict__ Jextra,
                                                     const float* __restrict__ outv) {
    __shared__ __align__(16) float sreg[32 * 68];
    __shared__ __align__(16) ull sv2[32 * 48];
    float* svh = (float*)sv2;
    int b0 = blockIdx.x * 32;
    int seg = blockIdx.y;
    int tid = threadIdx.x;
    int ty = tid / 16, tx = tid % 16;
    int j0 = ty * 4;
    ull acc2[4][3];
#pragma unroll
    for (int i = 0; i < 4; i++)
#pragma unroll
        for (int d = 0; d < 3; d++) acc2[i][d] = 0ull;

    int kbeg = seg * SEGLEN;
    for (int k0 = kbeg; k0 < kbeg + SEGLEN; k0 += 32) {
        for (int idx = tid; idx < 64 * 32; idx += 256) {
            int j = idx >> 5, vv = idx & 31;
            int gk = k0 + vv;
            float val = 0.f;
            if (j < J54 && gk < NV) {
                const float* row = reg_row(j, Jreg, Jspin, Jextra);
                val = row[gk];
            }
            sreg[vv * 68 + j] = val;
        }
        for (int idx = tid; idx < 32 * 48; idx += 256) {
            int bb = idx / 48, r2 = idx % 48;
            float2 val = *(const float2*)(outv + (size_t)(b0 + bb) * N3 + k0 * 3 + r2 * 2);
            int rem = r2 * 2;
            int f0 = rem / 3, d0 = rem % 3;
            int f1 = (rem + 1) / 3, d1 = (rem + 1) % 3;
            int half = bb & 1, pr = bb >> 1;
            svh[(f0 * 48 + pr * 3 + d0) * 2 + half] = val.x;
            svh[(f1 * 48 + pr * 3 + d1) * 2 + half] = val.y;
        }
        __syncthreads();
#pragma unroll
        for (int vv = 0; vv < 32; vv++) {
            float4 a = *(const float4*)&sreg[vv * 68 + j0];
            ull ax = pk2(a.x, a.x), ay = pk2(a.y, a.y);
            ull az = pk2(a.z, a.z), aw = pk2(a.w, a.w);
            ull bx = sv2[vv * 48 + tx * 3 + 0];
            ull by = sv2[vv * 48 + tx * 3 + 1];
            ull bz = sv2[vv * 48 + tx * 3 + 2];
            acc2[0][0] = ffma2(ax, bx, acc2[0][0]);
            acc2[0][1] = ffma2(ax, by, acc2[0][1]);
            acc2[0][2] = ffma2(ax, bz, acc2[0][2]);
            acc2[1][0] = ffma2(ay, bx, acc2[1][0]);
            acc2[1][1] = ffma2(ay, by, acc2[1][1]);
            acc2[1][2] = ffma2(ay, bz, acc2[1][2]);
            acc2[2][0] = ffma2(az, bx, acc2[2][0]);
            acc2[2][1] = ffma2(az, by, acc2[2][1]);
            acc2[2][2] = ffma2(az, bz, acc2[2][2]);
            acc2[3][0] = ffma2(aw, bx, acc2[3][0]);
            acc2[3][1] = ffma2(aw, by, acc2[3][1]);
            acc2[3][2] = ffma2(aw, bz, acc2[3][2]);
        }
        __syncthreads();
    }
    int ba = b0 + 2 * tx, bb2 = ba + 1;
#pragma unroll
    for (int i = 0; i < 4; i++) {
        int j = j0 + i;
        if (j < J54) {
#pragma unroll
            for (int d = 0; d < 3; d++) {
                float xa, xb;
                upk2(acc2[i][d], xa, xb);
                g_part[((size_t)(seg * BATCH + ba) * J54 + j) * 3 + d] = xa;
                g_part[((size_t)(seg * BATCH + bb2) * J54 + j) * 3 + d] = xb;
            }
        }
    }
}

// ============================================================================
// finalize: sum partials, pelvis, write joints & pelvis, then shift this
// batch's vertices in-place (merged subv).
// ============================================================================
__global__ void __launch_bounds__(256) finalize_kernel(const int* __restrict__ jmap,
                                                       float* __restrict__ out) {
    int b = blockIdx.x, t = threadIdx.x;
    __shared__ float jall[J54 * 3];
    __shared__ float pel[3];
    int is64 = g_jmap64;
    if (t < 162) {
        float s = 0.f;
        for (int seg = 0; seg < NSEG; seg++)
            s += g_part[(size_t)(seg * BATCH + b) * (J54 * 3) + t];
        jall[t] = s;
    }
    __syncthreads();
    if (t < 3) {
        int a = is64 ? jmap[2 * 27] : jmap[27];
        int c = is64 ? jmap[2 * 28] : jmap[28];
        float p = 0.5f * (jall[a * 3 + t] + jall[c * 3 + t]);
        pel[t] = p;
        out[(size_t)BATCH * N3 + (size_t)BATCH * 147 + b * 3 + t] = p;
    }
    __syncthreads();
    if (t < 147) {
        int i = t / 3, d = t % 3;
        int j = is64 ? jmap[2 * i] : jmap[i];
        out[(size_t)BATCH * N3 + b * 147 + t] = jall[j * 3 + d] - pel[d];
    }
    // merged subv: shift this batch's 20670 vertex floats (float2 pairs)
    float p0 = pel[0], p1 = pel[1], p2 = pel[2];
    float* vb = out + (size_t)b * N3;
    for (int p = t; p < N3 / 2; p += 256) {
        int idx = 2 * p;
        int d0 = idx % 3;
        float2 v = *(float2*)(vb + idx);
        v.x -= (d0 == 0) ? p0 : (d0 == 1) ? p1 : p2;
        int d1 = (d0 + 1 == 3) ? 0 : d0 + 1;
        v.y -= (d1 == 0) ? p0 : (d1 == 1) ? p1 : p2;
        *(float2*)(vb + idx) = v;
    }
}

// ============================================================================
extern "C" void kernel_launch(void* const* d_in, const int* in_sizes, int n_in,
                              void* d_out, int out_size) {
    const float* pose      = (const float*)d_in[0];
    const float* beta      = (const float*)d_in[1];
    const float* vtemp     = (const float*)d_in[2];
    const float* shapedirs = (const float*)d_in[3];
    const float* posedirs  = (const float*)d_in[4];
    const float* weights   = (const float*)d_in[5];
    const float* Jreg      = (const float*)d_in[6];
    const float* Jspin     = (const float*)d_in[7];
    const float* Jextra    = (const float*)d_in[8];
    const int* jmap        = (const int*)d_in[10];
    float* out = (float*)d_out;

    // order chosen so launch index 3 (the ncu-captured one) is the GEMM
    pack_kernel<<<NP / 8, 224>>>(posedirs, shapedirs);              // 0
    jm_kernel<<<72, 256>>>(Jreg, shapedirs, vtemp);                 // 1
    pose_kernel<<<BATCH / 4, 128>>>(pose, beta);                    // 2
    gemm_bf16_kernel<<<dim3(BATCH / 128, NP / 128), 256>>>(vtemp);  // 3 <- profiled
    sniff_kernel<<<1, 32>>>(jmap);                                  // 4
    skin_kernel<<<dim3(54, BATCH / 16), 128>>>(weights, out);       // 5
    joints_kernel<<<dim3(BATCH / 32, NSEG), 256>>>(Jreg, Jspin, Jextra, out); // 6
    finalize_kernel<<<BATCH, 256>>>(jmap, out);                     // 7
}

// round 8
// speedup vs baseline: 1.6663x; 1.1983x over previous
#include <cuda_runtime.h>
#include <cuda_bf16.h>
#include <cstdint>

#define BATCH 512
#define NV 6890
#define N3 20670      // NV*3
#define NP 20736      // padded N: 162*128
#define KDIM 224      // 207 + 10 + 7 pad
#define NJ 24
#define J54 54
#define NSEG 8
#define SEGLEN 864

typedef unsigned long long ull;

__constant__ int c_parent[23] = {0, 0, 0, 1, 2, 3, 4, 5, 6, 7, 8, 9,
                                 9, 9, 12, 13, 14, 16, 17, 18, 19, 20, 21};

// ---- scratch ----
__device__ float g_JM[NJ * 3 * 11];
__device__ __nv_bfloat16 g_Ab[BATCH * KDIM];      // A row-major [b][k] bf16
__device__ __nv_bfloat16 g_Wb[(size_t)NP * KDIM]; // W row-major [n][k] bf16
__device__ float g_Gc[BATCH * NJ * 12];
__device__ float g_vposed[BATCH * N3];
__device__ float g_part[NSEG * BATCH * J54 * 3];
__device__ int g_jmap64;

__device__ __forceinline__ void mma_bf16(float* c, const uint32_t* a, const uint32_t* b) {
    asm volatile(
        "mma.sync.aligned.m16n8k16.row.col.f32.bf16.bf16.f32 "
        "{%0,%1,%2,%3}, {%4,%5,%6,%7}, {%8,%9}, {%0,%1,%2,%3};\n"
        : "+f"(c[0]), "+f"(c[1]), "+f"(c[2]), "+f"(c[3])
        : "r"(a[0]), "r"(a[1]), "r"(a[2]), "r"(a[3]), "r"(b[0]), "r"(b[1]));
}

// ---- packed fp32x2 ----
__device__ __forceinline__ ull pk2(float x, float y) {
    ull r;
    asm("mov.b64 %0, {%1, %2};" : "=l"(r) : "f"(x), "f"(y));
    return r;
}
__device__ __forceinline__ void upk2(ull v, float& x, float& y) {
    asm("mov.b64 {%0, %1}, %2;" : "=f"(x), "=f"(y) : "l"(v));
}
__device__ __forceinline__ ull ffma2(ull a, ull b, ull c) {
    ull r;
    asm("fma.rn.f32x2 %0, %1, %2, %3;" : "=l"(r) : "l"(a), "l"(b), "l"(c));
    return r;
}

__device__ __forceinline__ const float* reg_row(int r, const float* Jreg,
                                                const float* Jspin, const float* Jextra) {
    return (r < 24) ? (Jreg + r * NV)
         : (r < 45) ? (Jspin + (r - 24) * NV)
                    : (Jextra + (r - 45) * NV);
}

// ============================================================================
// prep: blocks [0, NP/8) pack W bf16; blocks [NP/8, NP/8+72) compute g_JM
// ============================================================================
__global__ void __launch_bounds__(256) prep_kernel(const float* __restrict__ posedirs,
                                                   const float* __restrict__ shapedirs,
                                                   const float* __restrict__ Jreg,
                                                   const float* __restrict__ vtemp) {
    int t = threadIdx.x;
    if (blockIdx.x < NP / 8) {
        int n0 = blockIdx.x * 8;
        if (t < KDIM) {
#pragma unroll
            for (int r = 0; r < 8; r++) {
                int n = n0 + r;
                float v = 0.f;
                if (n < N3) {
                    if (t < 207)      v = posedirs[(size_t)n * 207 + t];
                    else if (t < 217) v = shapedirs[n * 10 + (t - 207)];
                }
                g_Wb[(size_t)n * KDIM + t] = __float2bfloat16(v);
            }
        }
    } else {
        int blk = blockIdx.x - NP / 8;
        int j = blk / 3, d = blk % 3;
        float acc[11];
#pragma unroll
        for (int k = 0; k < 11; k++) acc[k] = 0.f;
        const float* reg = Jreg + j * NV;
        for (int v = t; v < NV; v += 256) {
            float r = reg[v];
            const float* sd = shapedirs + (v * 3 + d) * 10;
#pragma unroll
            for (int k = 0; k < 10; k++) acc[k] += r * sd[k];
            acc[10] += r * vtemp[v * 3 + d];
        }
        __shared__ float red[256];
        for (int k = 0; k < 11; k++) {
            red[t] = acc[k];
            __syncthreads();
            for (int s = 128; s > 0; s >>= 1) {
                if (t < s) red[t] += red[t + s];
                __syncthreads();
            }
            if (t == 0) g_JM[(j * 3 + d) * 11 + k] = red[0];
            __syncthreads();
        }
    }
}

// ============================================================================
// pose: 4 batches per block; rodrigues, chain, Gc; writes bf16 A rows
// ============================================================================
__global__ void __launch_bounds__(128) pose_kernel(const float* __restrict__ pose,
                                                   const float* __restrict__ beta) {
    int w = threadIdx.x >> 5, t = threadIdx.x & 31;
    int b = blockIdx.x * 4 + w;
    __shared__ float sR[4][NJ][9];
    __shared__ float sJ[4][NJ][3];
    __shared__ float sA[4][NJ][12];

    if (t < NJ) {
        float rx = pose[b * 72 + 3 * t + 0];
        float ry = pose[b * 72 + 3 * t + 1];
        float rz = pose[b * 72 + 3 * t + 2];
        float th = sqrtf(rx * rx + ry * ry + rz * rz);
        float inv = 1.f / fmaxf(th, 1e-8f);
        float kx = rx * inv, ky = ry * inv, kz = rz * inv;
        float s = sinf(th), c = cosf(th), C = 1.f - c;
        float kn2 = kx * kx + ky * ky + kz * kz;
        float R[9];
        R[0] = 1.f + C * (kx * kx - kn2);
        R[1] = -s * kz + C * kx * ky;
        R[2] = s * ky + C * kx * kz;
        R[3] = s * kz + C * ky * kx;
        R[4] = 1.f + C * (ky * ky - kn2);
        R[5] = -s * kx + C * ky * kz;
        R[6] = -s * ky + C * kz * kx;
        R[7] = s * kx + C * kz * ky;
        R[8] = 1.f + C * (kz * kz - kn2);
#pragma unroll
        for (int e = 0; e < 9; e++) sR[w][t][e] = R[e];
        if (t >= 1) {
            __nv_bfloat16* dst = g_Ab + b * KDIM + (t - 1) * 9;
#pragma unroll
            for (int e = 0; e < 9; e++) {
                float val = R[e] - ((e == 0 || e == 4 || e == 8) ? 1.f : 0.f);
                dst[e] = __float2bfloat16(val);
            }
        }
#pragma unroll
        for (int d = 0; d < 3; d++) {
            const float* m = g_JM + (t * 3 + d) * 11;
            float val = m[10];
#pragma unroll
            for (int k = 0; k < 10; k++) val += m[k] * beta[b * 10 + k];
            sJ[w][t][d] = val;
        }
    }
    if (t == 0) {
#pragma unroll
        for (int k = 0; k < 10; k++)
            g_Ab[b * KDIM + 207 + k] = __float2bfloat16(beta[b * 10 + k]);
#pragma unroll
        for (int k = 217; k < KDIM; k++)
            g_Ab[b * KDIM + k] = __float2bfloat16(0.f);
    }
    __syncwarp();
    if (t == 0) {
#pragma unroll
        for (int e = 0; e < 9; e++) sA[w][0][(e / 3) * 4 + (e % 3)] = sR[w][0][e];
        sA[w][0][3] = sJ[w][0][0]; sA[w][0][7] = sJ[w][0][1]; sA[w][0][11] = sJ[w][0][2];
        for (int i = 1; i < NJ; i++) {
            int p = c_parent[i - 1];
            float lt0 = sJ[w][i][0] - sJ[w][p][0];
            float lt1 = sJ[w][i][1] - sJ[w][p][1];
            float lt2 = sJ[w][i][2] - sJ[w][p][2];
            for (int r = 0; r < 3; r++) {
                float p0 = sA[w][p][r * 4 + 0], p1 = sA[w][p][r * 4 + 1];
                float p2 = sA[w][p][r * 4 + 2], p3 = sA[w][p][r * 4 + 3];
                for (int cc = 0; cc < 3; cc++)
                    sA[w][i][r * 4 + cc] = p0 * sR[w][i][0 * 3 + cc] + p1 * sR[w][i][1 * 3 + cc] + p2 * sR[w][i][2 * 3 + cc];
                sA[w][i][r * 4 + 3] = p0 * lt0 + p1 * lt1 + p2 * lt2 + p3;
            }
        }
    }
    __syncwarp();
    if (t < NJ) {
        float j0 = sJ[w][t][0], j1 = sJ[w][t][1], j2 = sJ[w][t][2];
        float* dst = g_Gc + (b * NJ + t) * 12;
#pragma unroll
        for (int r = 0; r < 3; r++) {
            float a0 = sA[w][t][r * 4 + 0], a1 = sA[w][t][r * 4 + 1];
            float a2 = sA[w][t][r * 4 + 2], a3 = sA[w][t][r * 4 + 3];
            dst[r * 4 + 0] = a0; dst[r * 4 + 1] = a1; dst[r * 4 + 2] = a2;
            dst[r * 4 + 3] = a3 - (a0 * j0 + a1 * j1 + a2 * j2);
        }
    }
}

// ============================================================================
// GEMM bf16 m16n8k16: v_posed = A @ W^T + vtemp
// ============================================================================
__global__ void __launch_bounds__(256, 2) gemm_bf16_kernel(const float* __restrict__ vtemp) {
    __shared__ __align__(16) __nv_bfloat16 As[2][128][24];
    __shared__ __align__(16) __nv_bfloat16 Bs[2][128][24];
    int tid = threadIdx.x;
    int lane = tid & 31, wid = tid >> 5;
    int warp_m = wid & 1, warp_n = wid >> 1;
    int gq = lane >> 2, tq = lane & 3;
    int m0 = blockIdx.x * 128;
    int n0 = blockIdx.y * 128;

    float acc[4][4][4];
#pragma unroll
    for (int mt = 0; mt < 4; mt++)
#pragma unroll
        for (int nt = 0; nt < 4; nt++)
#pragma unroll
            for (int i = 0; i < 4; i++) acc[mt][nt][i] = 0.f;

    const int NSTAGE = KDIM / 16;
    const int mrow = tid >> 1, hh = tid & 1;

#define LOAD_STAGE(s, buf)                                                            \
    {                                                                                 \
        int k0 = (s) * 16;                                                            \
        unsigned da = (unsigned)__cvta_generic_to_shared(&As[buf][mrow][hh * 8]);     \
        const __nv_bfloat16* sa = g_Ab + (m0 + mrow) * KDIM + k0 + hh * 8;            \
        asm volatile("cp.async.cg.shared.global [%0], [%1], 16;" ::"r"(da), "l"(sa)); \
        unsigned db = (unsigned)__cvta_generic_to_shared(&Bs[buf][mrow][hh * 8]);     \
        const __nv_bfloat16* sb = g_Wb + (size_t)(n0 + mrow) * KDIM + k0 + hh * 8;    \
        asm volatile("cp.async.cg.shared.global [%0], [%1], 16;" ::"r"(db), "l"(sb)); \
        asm volatile("cp.async.commit_group;");                                       \
    }

    LOAD_STAGE(0, 0);
    for (int s = 0; s < NSTAGE; s++) {
        int buf = s & 1;
        if (s + 1 < NSTAGE) {
            LOAD_STAGE(s + 1, buf ^ 1);
            asm volatile("cp.async.wait_group 1;");
        } else {
            asm volatile("cp.async.wait_group 0;");
        }
        __syncthreads();
        const uint32_t* As32 = (const uint32_t*)&As[buf][0][0];
        const uint32_t* Bs32 = (const uint32_t*)&Bs[buf][0][0];
        uint32_t af[4][4], bf[4][2];
#pragma unroll
        for (int mt = 0; mt < 4; mt++) {
            int r = warp_m * 64 + mt * 16 + gq;
            af[mt][0] = As32[r * 12 + tq];
            af[mt][1] = As32[(r + 8) * 12 + tq];
            af[mt][2] = As32[r * 12 + 4 + tq];
            af[mt][3] = As32[(r + 8) * 12 + 4 + tq];
        }
#pragma unroll
        for (int nt = 0; nt < 4; nt++) {
            int cn = warp_n * 32 + nt * 8 + gq;
            bf[nt][0] = Bs32[cn * 12 + tq];
            bf[nt][1] = Bs32[cn * 12 + 4 + tq];
        }
#pragma unroll
        for (int mt = 0; mt < 4; mt++)
#pragma unroll
            for (int nt = 0; nt < 4; nt++)
                mma_bf16(acc[mt][nt], af[mt], bf[nt]);
        __syncthreads();
    }

#pragma unroll
    for (int mt = 0; mt < 4; mt++) {
        int row = m0 + warp_m * 64 + mt * 16 + gq;
#pragma unroll
        for (int nt = 0; nt < 4; nt++) {
            int cn = n0 + warp_n * 32 + nt * 8 + 2 * tq;
            if (cn < N3) {
                float2 vt = *(const float2*)(vtemp + cn);
                float2 o0 = {acc[mt][nt][0] + vt.x, acc[mt][nt][1] + vt.y};
                float2 o1 = {acc[mt][nt][2] + vt.x, acc[mt][nt][3] + vt.y};
                *(float2*)(g_vposed + (size_t)row * N3 + cn) = o0;
                *(float2*)(g_vposed + (size_t)(row + 8) * N3 + cn) = o1;
            }
        }
    }
#undef LOAD_STAGE
}

// ============================================================================
__global__ void sniff_kernel(const int* __restrict__ jmap) {
    int t = threadIdx.x;
    int bad = (t < 24 && jmap[2 * t + 1] != 0) ? 1 : 0;
    unsigned m = __ballot_sync(0xffffffff, bad);
    if (t == 0) g_jmap64 = (m == 0) ? 1 : 0;
}

// ============================================================================
// skin: 2 verts/thread x 16 batches (8 pairs) per block. Each Gc broadcast
// LDS.128 now feeds 4 ffma2 (two vertices), halving the shared-pipe stream.
// ============================================================================
__global__ void __launch_bounds__(128) skin_kernel(const float* __restrict__ weights,
                                                   float* __restrict__ out) {
    __shared__ __align__(16) ull sGc2[8 * 288];
    int b0 = blockIdx.y * 16;
    int t = threadIdx.x;
    int vA = blockIdx.x * 256 + t;        // grid.x = 27 (27*256 = 6912)
    int vB = vA + 128;
    for (int idx = t; idx < 8 * 288; idx += 128) {
        int p = idx / 288, e = idx % 288;
        sGc2[idx] = pk2(g_Gc[(size_t)(b0 + 2 * p) * 288 + e],
                        g_Gc[(size_t)(b0 + 2 * p + 1) * 288 + e]);
    }
    __syncthreads();
    bool okA = vA < NV, okB = vB < NV;
    float wA[NJ], wB[NJ];
    {
        const float4* wa = (const float4*)(weights + (size_t)vA * NJ);
        const float4* wb = (const float4*)(weights + (size_t)vB * NJ);
#pragma unroll
        for (int i = 0; i < 6; i++) {
            float4 x = okA ? wa[i] : make_float4(0.f, 0.f, 0.f, 0.f);
            wA[4 * i + 0] = x.x; wA[4 * i + 1] = x.y; wA[4 * i + 2] = x.z; wA[4 * i + 3] = x.w;
            float4 y = okB ? wb[i] : make_float4(0.f, 0.f, 0.f, 0.f);
            wB[4 * i + 0] = y.x; wB[4 * i + 1] = y.y; wB[4 * i + 2] = y.z; wB[4 * i + 3] = y.w;
        }
    }
#pragma unroll 1
    for (int p = 0; p < 8; p++) {
        ull TA[12], TB[12];
#pragma unroll
        for (int c = 0; c < 12; c++) { TA[c] = 0ull; TB[c] = 0ull; }
        const ulonglong2* gc = (const ulonglong2*)(sGc2 + p * 288);
#pragma unroll
        for (int j = 0; j < NJ; j++) {
            ull wa2 = pk2(wA[j], wA[j]);
            ull wb2 = pk2(wB[j], wB[j]);
#pragma unroll
            for (int i = 0; i < 6; i++) {
                ulonglong2 g2 = gc[j * 6 + i];
                TA[2 * i + 0] = ffma2(wa2, g2.x, TA[2 * i + 0]);
                TA[2 * i + 1] = ffma2(wa2, g2.y, TA[2 * i + 1]);
                TB[2 * i + 0] = ffma2(wb2, g2.x, TB[2 * i + 0]);
                TB[2 * i + 1] = ffma2(wb2, g2.y, TB[2 * i + 1]);
            }
        }
        int ba = b0 + 2 * p, bb = ba + 1;
        if (okA) {
            const float* vpa = g_vposed + (size_t)ba * N3 + vA * 3;
            const float* vpb = g_vposed + (size_t)bb * N3 + vA * 3;
            ull px = pk2(vpa[0], vpb[0]);
            ull py = pk2(vpa[1], vpb[1]);
            ull pz = pk2(vpa[2], vpb[2]);
            float* oa = out + (size_t)ba * N3 + vA * 3;
            float* ob = out + (size_t)bb * N3 + vA * 3;
#pragma unroll
            for (int r = 0; r < 3; r++) {
                ull o2 = ffma2(TA[4 * r + 0], px,
                         ffma2(TA[4 * r + 1], py,
                         ffma2(TA[4 * r + 2], pz, TA[4 * r + 3])));
                float xa, xb;
                upk2(o2, xa, xb);
                oa[r] = xa; ob[r] = xb;
            }
        }
        if (okB) {
            const float* vpa = g_vposed + (size_t)ba * N3 + vB * 3;
            const float* vpb = g_vposed + (size_t)bb * N3 + vB * 3;
            ull px = pk2(vpa[0], vpb[0]);
            ull py = pk2(vpa[1], vpb[1]);
            ull pz = pk2(vpa[2], vpb[2]);
            float* oa = out + (size_t)ba * N3 + vB * 3;
            float* ob = out + (size_t)bb * N3 + vB * 3;
#pragma unroll
            for (int r = 0; r < 3; r++) {
                ull o2 = ffma2(TB[4 * r + 0], px,
                         ffma2(TB[4 * r + 1], py,
                         ffma2(TB[4 * r + 2], pz, TB[4 * r + 3])));
                float xa, xb;
                upk2(o2, xa, xb);
                oa[r] = xa; ob[r] = xb;
            }
        }
    }
}

// ============================================================================
// joints: 16 batches/block (8 packed pairs), 2 joints/thread, grid (32, 8)
// ============================================================================
__global__ void __launch_bounds__(256) joints_kernel(const float* __restrict__ Jreg,
                                                     const float* __restrict__ Jspin,
                                                     const float* __restrict__ Jextra,
                                                     const float* __restrict__ outv) {
    __shared__ __align__(16) float sreg[32 * 68];
    __shared__ __align__(16) ull sv2[32 * 24];
    float* svh = (float*)sv2;
    int b0 = blockIdx.x * 16;   // grid.x = 32
    int seg = blockIdx.y;
    int tid = threadIdx.x;
    int tx = tid & 7, ty = tid >> 3;   // tx: pair, ty: 0..31 -> 2 joints
    int j0 = ty * 2;
    ull acc2[2][3];
#pragma unroll
    for (int i = 0; i < 2; i++)
#pragma unroll
        for (int d = 0; d < 3; d++) acc2[i][d] = 0ull;

    int kbeg = seg * SEGLEN;
    for (int k0 = kbeg; k0 < kbeg + SEGLEN; k0 += 32) {
        for (int idx = tid; idx < 64 * 32; idx += 256) {
            int j = idx >> 5, vv = idx & 31;
            int gk = k0 + vv;
            float val = 0.f;
            if (j < J54 && gk < NV) {
                const float* row = reg_row(j, Jreg, Jspin, Jextra);
                val = row[gk];
            }
            sreg[vv * 68 + j] = val;
        }
        for (int idx = tid; idx < 16 * 48; idx += 256) {
            int bb = idx / 48, r2 = idx % 48;
            float2 val = *(const float2*)(outv + (size_t)(b0 + bb) * N3 + k0 * 3 + r2 * 2);
            int rem = r2 * 2;
            int f0 = rem / 3, d0 = rem % 3;
            int f1 = (rem + 1) / 3, d1 = (rem + 1) % 3;
            int half = bb & 1, pr = bb >> 1;
            svh[(f0 * 24 + pr * 3 + d0) * 2 + half] = val.x;
            svh[(f1 * 24 + pr * 3 + d1) * 2 + half] = val.y;
        }
        __syncthreads();
#pragma unroll
        for (int vv = 0; vv < 32; vv++) {
            float2 a = *(const float2*)&sreg[vv * 68 + j0];
            ull a0 = pk2(a.x, a.x), a1 = pk2(a.y, a.y);
            ull bx = sv2[vv * 24 + tx * 3 + 0];
            ull by = sv2[vv * 24 + tx * 3 + 1];
            ull bz = sv2[vv * 24 + tx * 3 + 2];
            acc2[0][0] = ffma2(a0, bx, acc2[0][0]);
            acc2[0][1] = ffma2(a0, by, acc2[0][1]);
            acc2[0][2] = ffma2(a0, bz, acc2[0][2]);
            acc2[1][0] = ffma2(a1, bx, acc2[1][0]);
            acc2[1][1] = ffma2(a1, by, acc2[1][1]);
            acc2[1][2] = ffma2(a1, bz, acc2[1][2]);
        }
        __syncthreads();
    }
    int ba = b0 + 2 * tx, bb2 = ba + 1;
#pragma unroll
    for (int i = 0; i < 2; i++) {
        int j = j0 + i;
        if (j < J54) {
#pragma unroll
            for (int d = 0; d < 3; d++) {
                float xa, xb;
                upk2(acc2[i][d], xa, xb);
                g_part[((size_t)(seg * BATCH + ba) * J54 + j) * 3 + d] = xa;
                g_part[((size_t)(seg * BATCH + bb2) * J54 + j) * 3 + d] = xb;
            }
        }
    }
}

// ============================================================================
// finalize: sum partials, pelvis, write joints & pelvis, shift vertices
// ============================================================================
__global__ void __launch_bounds__(256) finalize_kernel(const int* __restrict__ jmap,
                                                       float* __restrict__ out) {
    int b = blockIdx.x, t = threadIdx.x;
    __shared__ float jall[J54 * 3];
    __shared__ float pel[3];
    int is64 = g_jmap64;
    if (t < 162) {
        float s = 0.f;
        for (int seg = 0; seg < NSEG; seg++)
            s += g_part[(size_t)(seg * BATCH + b) * (J54 * 3) + t];
        jall[t] = s;
    }
    __syncthreads();
    if (t < 3) {
        int a = is64 ? jmap[2 * 27] : jmap[27];
        int c = is64 ? jmap[2 * 28] : jmap[28];
        float p = 0.5f * (jall[a * 3 + t] + jall[c * 3 + t]);
        pel[t] = p;
        out[(size_t)BATCH * N3 + (size_t)BATCH * 147 + b * 3 + t] = p;
    }
    __syncthreads();
    if (t < 147) {
        int i = t / 3, d = t % 3;
        int j = is64 ? jmap[2 * i] : jmap[i];
        out[(size_t)BATCH * N3 + b * 147 + t] = jall[j * 3 + d] - pel[d];
    }
    float p0 = pel[0], p1 = pel[1], p2 = pel[2];
    float* vb = out + (size_t)b * N3;
    for (int p = t; p < N3 / 2; p += 256) {
        int idx = 2 * p;
        int d0 = idx % 3;
        float2 v = *(float2*)(vb + idx);
        v.x -= (d0 == 0) ? p0 : (d0 == 1) ? p1 : p2;
        int d1 = (d0 + 1 == 3) ? 0 : d0 + 1;
        v.y -= (d1 == 0) ? p0 : (d1 == 1) ? p1 : p2;
        *(float2*)(vb + idx) = v;
    }
}

// ============================================================================
extern "C" void kernel_launch(void* const* d_in, const int* in_sizes, int n_in,
                              void* d_out, int out_size) {
    const float* pose      = (const float*)d_in[0];
    const float* beta      = (const float*)d_in[1];
    const float* vtemp     = (const float*)d_in[2];
    const float* shapedirs = (const float*)d_in[3];
    const float* posedirs  = (const float*)d_in[4];
    const float* weights   = (const float*)d_in[5];
    const float* Jreg      = (const float*)d_in[6];
    const float* Jspin     = (const float*)d_in[7];
    const float* Jextra    = (const float*)d_in[8];
    const int* jmap        = (const int*)d_in[10];
    float* out = (float*)d_out;

    prep_kernel<<<NP / 8 + 72, 256>>>(posedirs, shapedirs, Jreg, vtemp); // 0
    pose_kernel<<<BATCH / 4, 128>>>(pose, beta);                         // 1
    gemm_bf16_kernel<<<dim3(BATCH / 128, NP / 128), 256>>>(vtemp);       // 2
    skin_kernel<<<dim3(27, BATCH / 16), 128>>>(weights, out);            // 3 <- profiled
    sniff_kernel<<<1, 32>>>(jmap);                                       // 4
    joints_kernel<<<dim3(BATCH / 16, NSEG), 256>>>(Jreg, Jspin, Jextra, out); // 5
    finalize_kernel<<<BATCH, 256>>>(jmap, out);                          // 6
}

// round 9
// speedup vs baseline: 2.1266x; 1.2762x over previous
#include <cuda_runtime.h>
#include <cuda_bf16.h>
#include <cstdint>

#define BATCH 512
#define NV 6890
#define N3 20670      // NV*3
#define NP 20736      // padded N: 162*128
#define KDIM 224      // 207 + 10 + 7 pad
#define NJ 24
#define J54 54
#define NSEG 16
#define SEGLEN 448    // 14*32 ; 16*448 = 7168 >= 6890

typedef unsigned long long ull;

__constant__ int c_parent[23] = {0, 0, 0, 1, 2, 3, 4, 5, 6, 7, 8, 9,
                                 9, 9, 12, 13, 14, 16, 17, 18, 19, 20, 21};

// ---- scratch ----
__device__ float g_JM[NJ * 3 * 11];
__device__ __nv_bfloat16 g_Ab[BATCH * KDIM];      // A row-major [b][k] bf16
__device__ __nv_bfloat16 g_Wb[(size_t)NP * KDIM]; // W row-major [n][k] bf16
__device__ float g_Gc[BATCH * NJ * 12];
__device__ float g_vposed[BATCH * N3];
__device__ float g_part[NSEG * BATCH * J54 * 3];
__device__ int g_jmap64;

__device__ __forceinline__ void mma_bf16(float* c, const uint32_t* a, const uint32_t* b) {
    asm volatile(
        "mma.sync.aligned.m16n8k16.row.col.f32.bf16.bf16.f32 "
        "{%0,%1,%2,%3}, {%4,%5,%6,%7}, {%8,%9}, {%0,%1,%2,%3};\n"
        : "+f"(c[0]), "+f"(c[1]), "+f"(c[2]), "+f"(c[3])
        : "r"(a[0]), "r"(a[1]), "r"(a[2]), "r"(a[3]), "r"(b[0]), "r"(b[1]));
}

// ---- packed fp32x2 ----
__device__ __forceinline__ ull pk2(float x, float y) {
    ull r;
    asm("mov.b64 %0, {%1, %2};" : "=l"(r) : "f"(x), "f"(y));
    return r;
}
__device__ __forceinline__ void upk2(ull v, float& x, float& y) {
    asm("mov.b64 {%0, %1}, %2;" : "=f"(x), "=f"(y) : "l"(v));
}
__device__ __forceinline__ ull ffma2(ull a, ull b, ull c) {
    ull r;
    asm("fma.rn.f32x2 %0, %1, %2, %3;" : "=l"(r) : "l"(a), "l"(b), "l"(c));
    return r;
}

__device__ __forceinline__ const float* reg_row(int r, const float* Jreg,
                                                const float* Jspin, const float* Jextra) {
    return (r < 24) ? (Jreg + r * NV)
         : (r < 45) ? (Jspin + (r - 24) * NV)
                    : (Jextra + (r - 45) * NV);
}

// ============================================================================
// prep: blocks [0, NP/8) pack W bf16; blocks [NP/8, NP/8+72) compute g_JM
// ============================================================================
__global__ void __launch_bounds__(256) prep_kernel(const float* __restrict__ posedirs,
                                                   const float* __restrict__ shapedirs,
                                                   const float* __restrict__ Jreg,
                                                   const float* __restrict__ vtemp) {
    int t = threadIdx.x;
    if (blockIdx.x < NP / 8) {
        int n0 = blockIdx.x * 8;
        if (t < KDIM) {
#pragma unroll
            for (int r = 0; r < 8; r++) {
                int n = n0 + r;
                float v = 0.f;
                if (n < N3) {
                    if (t < 207)      v = posedirs[(size_t)n * 207 + t];
                    else if (t < 217) v = shapedirs[n * 10 + (t - 207)];
                }
                g_Wb[(size_t)n * KDIM + t] = __float2bfloat16(v);
            }
        }
    } else {
        int blk = blockIdx.x - NP / 8;
        int j = blk / 3, d = blk % 3;
        float acc[11];
#pragma unroll
        for (int k = 0; k < 11; k++) acc[k] = 0.f;
        const float* reg = Jreg + j * NV;
        for (int v = t; v < NV; v += 256) {
            float r = reg[v];
            const float* sd = shapedirs + (v * 3 + d) * 10;
#pragma unroll
            for (int k = 0; k < 10; k++) acc[k] += r * sd[k];
            acc[10] += r * vtemp[v * 3 + d];
        }
        __shared__ float red[256];
        for (int k = 0; k < 11; k++) {
            red[t] = acc[k];
            __syncthreads();
            for (int s = 128; s > 0; s >>= 1) {
                if (t < s) red[t] += red[t + s];
                __syncthreads();
            }
            if (t == 0) g_JM[(j * 3 + d) * 11 + k] = red[0];
            __syncthreads();
        }
    }
}

// ============================================================================
// pose: 4 batches per block; rodrigues, chain, Gc; writes bf16 A rows
// ============================================================================
__global__ void __launch_bounds__(128) pose_kernel(const float* __restrict__ pose,
                                                   const float* __restrict__ beta) {
    int w = threadIdx.x >> 5, t = threadIdx.x & 31;
    int b = blockIdx.x * 4 + w;
    __shared__ float sR[4][NJ][9];
    __shared__ float sJ[4][NJ][3];
    __shared__ float sA[4][NJ][12];

    if (t < NJ) {
        float rx = pose[b * 72 + 3 * t + 0];
        float ry = pose[b * 72 + 3 * t + 1];
        float rz = pose[b * 72 + 3 * t + 2];
        float th = sqrtf(rx * rx + ry * ry + rz * rz);
        float inv = 1.f / fmaxf(th, 1e-8f);
        float kx = rx * inv, ky = ry * inv, kz = rz * inv;
        float s = sinf(th), c = cosf(th), C = 1.f - c;
        float kn2 = kx * kx + ky * ky + kz * kz;
        float R[9];
        R[0] = 1.f + C * (kx * kx - kn2);
        R[1] = -s * kz + C * kx * ky;
        R[2] = s * ky + C * kx * kz;
        R[3] = s * kz + C * ky * kx;
        R[4] = 1.f + C * (ky * ky - kn2);
        R[5] = -s * kx + C * ky * kz;
        R[6] = -s * ky + C * kz * kx;
        R[7] = s * kx + C * kz * ky;
        R[8] = 1.f + C * (kz * kz - kn2);
#pragma unroll
        for (int e = 0; e < 9; e++) sR[w][t][e] = R[e];
        if (t >= 1) {
            __nv_bfloat16* dst = g_Ab + b * KDIM + (t - 1) * 9;
#pragma unroll
            for (int e = 0; e < 9; e++) {
                float val = R[e] - ((e == 0 || e == 4 || e == 8) ? 1.f : 0.f);
                dst[e] = __float2bfloat16(val);
            }
        }
#pragma unroll
        for (int d = 0; d < 3; d++) {
            const float* m = g_JM + (t * 3 + d) * 11;
            float val = m[10];
#pragma unroll
            for (int k = 0; k < 10; k++) val += m[k] * beta[b * 10 + k];
            sJ[w][t][d] = val;
        }
    }
    if (t == 0) {
#pragma unroll
        for (int k = 0; k < 10; k++)
            g_Ab[b * KDIM + 207 + k] = __float2bfloat16(beta[b * 10 + k]);
#pragma unroll
        for (int k = 217; k < KDIM; k++)
            g_Ab[b * KDIM + k] = __float2bfloat16(0.f);
    }
    __syncwarp();
    if (t == 0) {
#pragma unroll
        for (int e = 0; e < 9; e++) sA[w][0][(e / 3) * 4 + (e % 3)] = sR[w][0][e];
        sA[w][0][3] = sJ[w][0][0]; sA[w][0][7] = sJ[w][0][1]; sA[w][0][11] = sJ[w][0][2];
        for (int i = 1; i < NJ; i++) {
            int p = c_parent[i - 1];
            float lt0 = sJ[w][i][0] - sJ[w][p][0];
            float lt1 = sJ[w][i][1] - sJ[w][p][1];
            float lt2 = sJ[w][i][2] - sJ[w][p][2];
            for (int r = 0; r < 3; r++) {
                float p0 = sA[w][p][r * 4 + 0], p1 = sA[w][p][r * 4 + 1];
                float p2 = sA[w][p][r * 4 + 2], p3 = sA[w][p][r * 4 + 3];
                for (int cc = 0; cc < 3; cc++)
                    sA[w][i][r * 4 + cc] = p0 * sR[w][i][0 * 3 + cc] + p1 * sR[w][i][1 * 3 + cc] + p2 * sR[w][i][2 * 3 + cc];
                sA[w][i][r * 4 + 3] = p0 * lt0 + p1 * lt1 + p2 * lt2 + p3;
            }
        }
    }
    __syncwarp();
    if (t < NJ) {
        float j0 = sJ[w][t][0], j1 = sJ[w][t][1], j2 = sJ[w][t][2];
        float* dst = g_Gc + (b * NJ + t) * 12;
#pragma unroll
        for (int r = 0; r < 3; r++) {
            float a0 = sA[w][t][r * 4 + 0], a1 = sA[w][t][r * 4 + 1];
            float a2 = sA[w][t][r * 4 + 2], a3 = sA[w][t][r * 4 + 3];
            dst[r * 4 + 0] = a0; dst[r * 4 + 1] = a1; dst[r * 4 + 2] = a2;
            dst[r * 4 + 3] = a3 - (a0 * j0 + a1 * j1 + a2 * j2);
        }
    }
}

// ============================================================================
// GEMM bf16 m16n8k16: v_posed = A @ W^T + vtemp
// ============================================================================
__global__ void __launch_bounds__(256, 2) gemm_bf16_kernel(const float* __restrict__ vtemp) {
    __shared__ __align__(16) __nv_bfloat16 As[2][128][24];
    __shared__ __align__(16) __nv_bfloat16 Bs[2][128][24];
    int tid = threadIdx.x;
    int lane = tid & 31, wid = tid >> 5;
    int warp_m = wid & 1, warp_n = wid >> 1;
    int gq = lane >> 2, tq = lane & 3;
    int m0 = blockIdx.x * 128;
    int n0 = blockIdx.y * 128;

    float acc[4][4][4];
#pragma unroll
    for (int mt = 0; mt < 4; mt++)
#pragma unroll
        for (int nt = 0; nt < 4; nt++)
#pragma unroll
            for (int i = 0; i < 4; i++) acc[mt][nt][i] = 0.f;

    const int NSTAGE = KDIM / 16;
    const int mrow = tid >> 1, hh = tid & 1;

#define LOAD_STAGE(s, buf)                                                            \
    {                                                                                 \
        int k0 = (s) * 16;                                                            \
        unsigned da = (unsigned)__cvta_generic_to_shared(&As[buf][mrow][hh * 8]);     \
        const __nv_bfloat16* sa = g_Ab + (m0 + mrow) * KDIM + k0 + hh * 8;            \
        asm volatile("cp.async.cg.shared.global [%0], [%1], 16;" ::"r"(da), "l"(sa)); \
        unsigned db = (unsigned)__cvta_generic_to_shared(&Bs[buf][mrow][hh * 8]);     \
        const __nv_bfloat16* sb = g_Wb + (size_t)(n0 + mrow) * KDIM + k0 + hh * 8;    \
        asm volatile("cp.async.cg.shared.global [%0], [%1], 16;" ::"r"(db), "l"(sb)); \
        asm volatile("cp.async.commit_group;");                                       \
    }

    LOAD_STAGE(0, 0);
    for (int s = 0; s < NSTAGE; s++) {
        int buf = s & 1;
        if (s + 1 < NSTAGE) {
            LOAD_STAGE(s + 1, buf ^ 1);
            asm volatile("cp.async.wait_group 1;");
        } else {
            asm volatile("cp.async.wait_group 0;");
        }
        __syncthreads();
        const uint32_t* As32 = (const uint32_t*)&As[buf][0][0];
        const uint32_t* Bs32 = (const uint32_t*)&Bs[buf][0][0];
        uint32_t af[4][4], bf[4][2];
#pragma unroll
        for (int mt = 0; mt < 4; mt++) {
            int r = warp_m * 64 + mt * 16 + gq;
            af[mt][0] = As32[r * 12 + tq];
            af[mt][1] = As32[(r + 8) * 12 + tq];
            af[mt][2] = As32[r * 12 + 4 + tq];
            af[mt][3] = As32[(r + 8) * 12 + 4 + tq];
        }
#pragma unroll
        for (int nt = 0; nt < 4; nt++) {
            int cn = warp_n * 32 + nt * 8 + gq;
            bf[nt][0] = Bs32[cn * 12 + tq];
            bf[nt][1] = Bs32[cn * 12 + 4 + tq];
        }
#pragma unroll
        for (int mt = 0; mt < 4; mt++)
#pragma unroll
            for (int nt = 0; nt < 4; nt++)
                mma_bf16(acc[mt][nt], af[mt], bf[nt]);
        __syncthreads();
    }

#pragma unroll
    for (int mt = 0; mt < 4; mt++) {
        int row = m0 + warp_m * 64 + mt * 16 + gq;
#pragma unroll
        for (int nt = 0; nt < 4; nt++) {
            int cn = n0 + warp_n * 32 + nt * 8 + 2 * tq;
            if (cn < N3) {
                float2 vt = *(const float2*)(vtemp + cn);
                float2 o0 = {acc[mt][nt][0] + vt.x, acc[mt][nt][1] + vt.y};
                float2 o1 = {acc[mt][nt][2] + vt.x, acc[mt][nt][3] + vt.y};
                *(float2*)(g_vposed + (size_t)row * N3 + cn) = o0;
                *(float2*)(g_vposed + (size_t)(row + 8) * N3 + cn) = o1;
            }
        }
    }
#undef LOAD_STAGE
}

// ============================================================================
__global__ void sniff_kernel(const int* __restrict__ jmap) {
    int t = threadIdx.x;
    int bad = (t < 24 && jmap[2 * t + 1] != 0) ? 1 : 0;
    unsigned m = __ballot_sync(0xffffffff, bad);
    if (t == 0) g_jmap64 = (m == 0) ? 1 : 0;
}

// ============================================================================
// skin: 2 verts/thread x 16 batches (8 pairs) per block, software-pipelined
// vposed loads (pair p+1 prefetched into regs during pair p's T-build).
// ============================================================================
__global__ void __launch_bounds__(128) skin_kernel(const float* __restrict__ weights,
                                                   float* __restrict__ out) {
    __shared__ __align__(16) ull sGc2[8 * 288];
    int b0 = blockIdx.y * 16;
    int t = threadIdx.x;
    int vA = blockIdx.x * 256 + t;        // grid.x = 27
    int vB = vA + 128;
    for (int idx = t; idx < 8 * 288; idx += 128) {
        int p = idx / 288, e = idx % 288;
        sGc2[idx] = pk2(g_Gc[(size_t)(b0 + 2 * p) * 288 + e],
                        g_Gc[(size_t)(b0 + 2 * p + 1) * 288 + e]);
    }
    __syncthreads();
    bool okA = vA < NV, okB = vB < NV;
    float wA[NJ], wB[NJ];
    {
        const float4* wa = (const float4*)(weights + (size_t)vA * NJ);
        const float4* wb = (const float4*)(weights + (size_t)vB * NJ);
#pragma unroll
        for (int i = 0; i < 6; i++) {
            float4 x = okA ? wa[i] : make_float4(0.f, 0.f, 0.f, 0.f);
            wA[4 * i + 0] = x.x; wA[4 * i + 1] = x.y; wA[4 * i + 2] = x.z; wA[4 * i + 3] = x.w;
            float4 y = okB ? wb[i] : make_float4(0.f, 0.f, 0.f, 0.f);
            wB[4 * i + 0] = y.x; wB[4 * i + 1] = y.y; wB[4 * i + 2] = y.z; wB[4 * i + 3] = y.w;
        }
    }
    // prefetch registers: [vA even, vA odd, vB even, vB odd] x 3 coords
    float curA[6], curB[6], nxtA[6], nxtB[6];
#pragma unroll
    for (int i = 0; i < 6; i++) { curA[i] = 0.f; curB[i] = 0.f; nxtA[i] = 0.f; nxtB[i] = 0.f; }
    {
        const float* va = g_vposed + (size_t)b0 * N3;
        const float* vb = va + N3;
        if (okA) {
            curA[0] = va[vA * 3 + 0]; curA[1] = va[vA * 3 + 1]; curA[2] = va[vA * 3 + 2];
            curA[3] = vb[vA * 3 + 0]; curA[4] = vb[vA * 3 + 1]; curA[5] = vb[vA * 3 + 2];
        }
        if (okB) {
            curB[0] = va[vB * 3 + 0]; curB[1] = va[vB * 3 + 1]; curB[2] = va[vB * 3 + 2];
            curB[3] = vb[vB * 3 + 0]; curB[4] = vb[vB * 3 + 1]; curB[5] = vb[vB * 3 + 2];
        }
    }
#pragma unroll 1
    for (int p = 0; p < 8; p++) {
        // prefetch next pair's vposed while T-build runs
        if (p < 7) {
            const float* va = g_vposed + (size_t)(b0 + 2 * p + 2) * N3;
            const float* vb = va + N3;
            if (okA) {
                nxtA[0] = va[vA * 3 + 0]; nxtA[1] = va[vA * 3 + 1]; nxtA[2] = va[vA * 3 + 2];
                nxtA[3] = vb[vA * 3 + 0]; nxtA[4] = vb[vA * 3 + 1]; nxtA[5] = vb[vA * 3 + 2];
            }
            if (okB) {
                nxtB[0] = va[vB * 3 + 0]; nxtB[1] = va[vB * 3 + 1]; nxtB[2] = va[vB * 3 + 2];
                nxtB[3] = vb[vB * 3 + 0]; nxtB[4] = vb[vB * 3 + 1]; nxtB[5] = vb[vB * 3 + 2];
            }
        }
        ull TA[12], TB[12];
#pragma unroll
        for (int c = 0; c < 12; c++) { TA[c] = 0ull; TB[c] = 0ull; }
        const ulonglong2* gc = (const ulonglong2*)(sGc2 + p * 288);
#pragma unroll
        for (int j = 0; j < NJ; j++) {
            ull wa2 = pk2(wA[j], wA[j]);
            ull wb2 = pk2(wB[j], wB[j]);
#pragma unroll
            for (int i = 0; i < 6; i++) {
                ulonglong2 g2 = gc[j * 6 + i];
                TA[2 * i + 0] = ffma2(wa2, g2.x, TA[2 * i + 0]);
                TA[2 * i + 1] = ffma2(wa2, g2.y, TA[2 * i + 1]);
                TB[2 * i + 0] = ffma2(wb2, g2.x, TB[2 * i + 0]);
                TB[2 * i + 1] = ffma2(wb2, g2.y, TB[2 * i + 1]);
            }
        }
        int ba = b0 + 2 * p, bb = ba + 1;
        if (okA) {
            ull px = pk2(curA[0], curA[3]);
            ull py = pk2(curA[1], curA[4]);
            ull pz = pk2(curA[2], curA[5]);
            float* oa = out + (size_t)ba * N3 + vA * 3;
            float* ob = out + (size_t)bb * N3 + vA * 3;
#pragma unroll
            for (int r = 0; r < 3; r++) {
                ull o2 = ffma2(TA[4 * r + 0], px,
                         ffma2(TA[4 * r + 1], py,
                         ffma2(TA[4 * r + 2], pz, TA[4 * r + 3])));
                float xa, xb;
                upk2(o2, xa, xb);
                oa[r] = xa; ob[r] = xb;
            }
        }
        if (okB) {
            ull px = pk2(curB[0], curB[3]);
            ull py = pk2(curB[1], curB[4]);
            ull pz = pk2(curB[2], curB[5]);
            float* oa = out + (size_t)ba * N3 + vB * 3;
            float* ob = out + (size_t)bb * N3 + vB * 3;
#pragma unroll
            for (int r = 0; r < 3; r++) {
                ull o2 = ffma2(TB[4 * r + 0], px,
                         ffma2(TB[4 * r + 1], py,
                         ffma2(TB[4 * r + 2], pz, TB[4 * r + 3])));
                float xa, xb;
                upk2(o2, xa, xb);
                oa[r] = xa; ob[r] = xb;
            }
        }
#pragma unroll
        for (int i = 0; i < 6; i++) { curA[i] = nxtA[i]; curB[i] = nxtB[i]; }
    }
}

// ============================================================================
// joints: 16 batches/block, 2 joints/thread, grid (32, 16).
// Register-prefetch double buffer: commit(k) -> sync -> prefetch(k+1) -> compute(k) -> sync
// ============================================================================
__global__ void __launch_bounds__(256) joints_kernel(const float* __restrict__ Jreg,
                                                     const float* __restrict__ Jspin,
                                                     const float* __restrict__ Jextra,
                                                     const float* __restrict__ outv) {
    __shared__ __align__(16) float sreg[32 * 68];
    __shared__ __align__(16) ull sv2[32 * 24];
    int b0 = blockIdx.x * 16;   // grid.x = 32
    int seg = blockIdx.y;       // grid.y = 16
    int tid = threadIdx.x;
    int tx = tid & 7, ty = tid >> 3;
    int j0 = ty * 2;
    ull acc2[2][3];
#pragma unroll
    for (int i = 0; i < 2; i++)
#pragma unroll
        for (int d = 0; d < 3; d++) acc2[i][d] = 0ull;

    // prefetch registers
    float rga[8];
    float4 sva[2];
    int kbeg = seg * SEGLEN;

    // --- prefetch first tile ---
    {
        int k0 = kbeg;
#pragma unroll
        for (int i = 0; i < 8; i++) {
            int idx = tid + i * 256;
            int j = idx >> 5, vv = idx & 31;
            int gk = k0 + vv;
            float val = 0.f;
            if (j < J54 && gk < NV) val = reg_row(j, Jreg, Jspin, Jextra)[gk];
            rga[i] = val;
        }
#pragma unroll
        for (int q = 0; q < 2; q++) {
            int idx = tid + q * 256;
            if (idx < 384) {
                int pr = idx / 48, r2 = idx % 48;
                const float* pa = outv + (size_t)(b0 + 2 * pr) * N3 + k0 * 3 + r2 * 2;
                float2 ea = *(const float2*)pa;
                float2 eb = *(const float2*)(pa + N3);
                sva[q] = make_float4(ea.x, ea.y, eb.x, eb.y);
            }
        }
    }

    for (int k0 = kbeg; k0 < kbeg + SEGLEN; k0 += 32) {
        // commit prefetched tile to smem
#pragma unroll
        for (int i = 0; i < 8; i++) {
            int idx = tid + i * 256;
            sreg[(idx & 31) * 68 + (idx >> 5)] = rga[i];
        }
#pragma unroll
        for (int q = 0; q < 2; q++) {
            int idx = tid + q * 256;
            if (idx < 384) {
                int pr = idx / 48, r2 = idx % 48;
                int rem = r2 * 2;
                int f0 = rem / 3, d0 = rem % 3;
                int f1 = (rem + 1) / 3, d1 = (rem + 1) % 3;
                sv2[f0 * 24 + pr * 3 + d0] = pk2(sva[q].x, sva[q].z);
                sv2[f1 * 24 + pr * 3 + d1] = pk2(sva[q].y, sva[q].w);
            }
        }
        __syncthreads();
        // prefetch next tile (LDGs fly during compute)
        int kn = k0 + 32;
        if (kn < kbeg + SEGLEN) {
#pragma unroll
            for (int i = 0; i < 8; i++) {
                int idx = tid + i * 256;
                int j = idx >> 5, vv = idx & 31;
                int gk = kn + vv;
                float val = 0.f;
                if (j < J54 && gk < NV) val = reg_row(j, Jreg, Jspin, Jextra)[gk];
                rga[i] = val;
            }
#pragma unroll
            for (int q = 0; q < 2; q++) {
                int idx = tid + q * 256;
                if (idx < 384) {
                    int pr = idx / 48, r2 = idx % 48;
                    const float* pa = outv + (size_t)(b0 + 2 * pr) * N3 + kn * 3 + r2 * 2;
                    float2 ea = *(const float2*)pa;
                    float2 eb = *(const float2*)(pa + N3);
                    sva[q] = make_float4(ea.x, ea.y, eb.x, eb.y);
                }
            }
        }
        // compute from smem
#pragma unroll
        for (int vv = 0; vv < 32; vv++) {
            float2 a = *(const float2*)&sreg[vv * 68 + j0];
            ull a0 = pk2(a.x, a.x), a1 = pk2(a.y, a.y);
            ull bx = sv2[vv * 24 + tx * 3 + 0];
            ull by = sv2[vv * 24 + tx * 3 + 1];
            ull bz = sv2[vv * 24 + tx * 3 + 2];
            acc2[0][0] = ffma2(a0, bx, acc2[0][0]);
            acc2[0][1] = ffma2(a0, by, acc2[0][1]);
            acc2[0][2] = ffma2(a0, bz, acc2[0][2]);
            acc2[1][0] = ffma2(a1, bx, acc2[1][0]);
            acc2[1][1] = ffma2(a1, by, acc2[1][1]);
            acc2[1][2] = ffma2(a1, bz, acc2[1][2]);
        }
        __syncthreads();
    }
    int ba = b0 + 2 * tx, bb2 = ba + 1;
#pragma unroll
    for (int i = 0; i < 2; i++) {
        int j = j0 + i;
        if (j < J54) {
#pragma unroll
            for (int d = 0; d < 3; d++) {
                float xa, xb;
                upk2(acc2[i][d], xa, xb);
                g_part[((size_t)(seg * BATCH + ba) * J54 + j) * 3 + d] = xa;
                g_part[((size_t)(seg * BATCH + bb2) * J54 + j) * 3 + d] = xb;
            }
        }
    }
}

// ============================================================================
// finalize: sum partials, pelvis, write joints & pelvis, shift vertices
// ============================================================================
__global__ void __launch_bounds__(256) finalize_kernel(const int* __restrict__ jmap,
                                                       float* __restrict__ out) {
    int b = blockIdx.x, t = threadIdx.x;
    __shared__ float jall[J54 * 3];
    __shared__ float pel[3];
    int is64 = g_jmap64;
    if (t < 162) {
        float s = 0.f;
        for (int seg = 0; seg < NSEG; seg++)
            s += g_part[(size_t)(seg * BATCH + b) * (J54 * 3) + t];
        jall[t] = s;
    }
    __syncthreads();
    if (t < 3) {
        int a = is64 ? jmap[2 * 27] : jmap[27];
        int c = is64 ? jmap[2 * 28] : jmap[28];
        float p = 0.5f * (jall[a * 3 + t] + jall[c * 3 + t]);
        pel[t] = p;
        out[(size_t)BATCH * N3 + (size_t)BATCH * 147 + b * 3 + t] = p;
    }
    __syncthreads();
    if (t < 147) {
        int i = t / 3, d = t % 3;
        int j = is64 ? jmap[2 * i] : jmap[i];
        out[(size_t)BATCH * N3 + b * 147 + t] = jall[j * 3 + d] - pel[d];
    }
    float p0 = pel[0], p1 = pel[1], p2 = pel[2];
    float* vb = out + (size_t)b * N3;
    for (int p = t; p < N3 / 2; p += 256) {
        int idx = 2 * p;
        int d0 = idx % 3;
        float2 v = *(float2*)(vb + idx);
        v.x -= (d0 == 0) ? p0 : (d0 == 1) ? p1 : p2;
        int d1 = (d0 + 1 == 3) ? 0 : d0 + 1;
        v.y -= (d1 == 0) ? p0 : (d1 == 1) ? p1 : p2;
        *(float2*)(vb + idx) = v;
    }
}

// ============================================================================
extern "C" void kernel_launch(void* const* d_in, const int* in_sizes, int n_in,
                              void* d_out, int out_size) {
    const float* pose      = (const float*)d_in[0];
    const float* beta      = (const float*)d_in[1];
    const float* vtemp     = (const float*)d_in[2];
    const float* shapedirs = (const float*)d_in[3];
    const float* posedirs  = (const float*)d_in[4];
    const float* weights   = (const float*)d_in[5];
    const float* Jreg      = (const float*)d_in[6];
    const float* Jspin     = (const float*)d_in[7];
    const float* Jextra    = (const float*)d_in[8];
    const int* jmap        = (const int*)d_in[10];
    float* out = (float*)d_out;

    prep_kernel<<<NP / 8 + 72, 256>>>(posedirs, shapedirs, Jreg, vtemp); // 0
    pose_kernel<<<BATCH / 4, 128>>>(pose, beta);                         // 1
    gemm_bf16_kernel<<<dim3(BATCH / 128, NP / 128), 256>>>(vtemp);       // 2
    skin_kernel<<<dim3(27, BATCH / 16), 128>>>(weights, out);            // 3 <- profiled
    sniff_kernel<<<1, 32>>>(jmap);                                       // 4
    joints_kernel<<<dim3(BATCH / 16, NSEG), 256>>>(Jreg, Jspin, Jextra, out); // 5
    finalize_kernel<<<BATCH, 256>>>(jmap, out);                          // 6
}